// round 2
// baseline (speedup 1.0000x reference)
#include <cuda_runtime.h>
#include <stdint.h>
#include <stddef.h>

#define BB 2048
#define TT 100
#define EE 512
#define POSE 34
#define FUT 10
#define BE (BB*EE)

// ---------------- scratch (static device globals; no allocation) ----------------
__device__ float g_h1a[BE], g_h1b[BE], g_c1[BE];
__device__ float g_h2a[BE], g_h2b[BE], g_c2[BE];
__device__ float g_Wt1[560*2048];    // [k][n] k-major: rows 0..511 = enc1_Whh^T (perm), 512..545 = Wc^T (perm), 546..559 = 0
__device__ float g_Wt2[1024*2048];   // rows 0..511 = enc2_Wih^T, 512..1023 = enc2_Whh^T (perm)
__device__ float g_WtD1[512*2048];   // dec first step: dec1_Whh^T (perm)
__device__ float g_WtDr[512*2048];   // dec steps >=1: (dec1_Wih+dec1_Whh)^T (perm)
__device__ float g_b1[2048], g_b2[2048], g_bd[2048];
__device__ float g_preds[FUT*BE];

// ---------------- math helpers ----------------
__device__ __forceinline__ float sigmoidf_(float x) {
    return __fdividef(1.f, 1.f + __expf(-x));
}
__device__ __forceinline__ float tanhf_(float x) {
    return 1.f - __fdividef(2.f, __expf(2.f * x) + 1.f);
}

// ---------------- prep: transpose + gate-interleave permute ----------------
// perm: output column n corresponds to original gate row r = (n%4)*512 + n/4
// so columns 4e..4e+3 are (i,f,g,o) for hidden index e.
__global__ void prep_transpose(
    const float* __restrict__ e1Whh,
    const float* __restrict__ e2Wih, const float* __restrict__ e2Whh,
    const float* __restrict__ d1Wih, const float* __restrict__ d1Whh,
    const float* __restrict__ e2bih, const float* __restrict__ e2bhh,
    const float* __restrict__ d1bih, const float* __restrict__ d1bhh)
{
    long idx = (long)blockIdx.x * blockDim.x + threadIdx.x;
    const long TOTAL = 2560L * 2048L;
    if (idx >= TOTAL) return;
    int n = (int)(idx & 2047);
    int krow = (int)(idx >> 11);            // 0..2559
    int r = (n & 3) * 512 + (n >> 2);       // original gate row

    if (krow < 512) {
        g_Wt1[(long)krow * 2048 + n] = e1Whh[(long)r * 512 + krow];
    } else if (krow < 1024) {
        int k = krow - 512;
        g_Wt2[(long)k * 2048 + n] = e2Wih[(long)r * 512 + k];
    } else if (krow < 1536) {
        int k = krow - 1024;
        g_Wt2[(long)(512 + k) * 2048 + n] = e2Whh[(long)r * 512 + k];
    } else if (krow < 2048) {
        int k = krow - 1536;
        g_WtD1[(long)k * 2048 + n] = d1Whh[(long)r * 512 + k];
    } else {
        int k = krow - 2048;
        g_WtDr[(long)k * 2048 + n] = d1Wih[(long)r * 512 + k] + d1Whh[(long)r * 512 + k];
    }
    if (krow == 0) {
        g_b2[n] = e2bih[r] + e2bhh[r];
        g_bd[n] = d1bih[r] + d1bhh[r];
    }
}

// ---------------- prep: fold enc_lin into enc1 input path ----------------
// Wc[r][p] = sum_e enc1_Wih[r][e] * enc_lin_W[e][p]  -> stored at Wt1 rows 512+p (perm cols)
// b1[n]    = enc1_Wih[r]·enc_lin_b + enc1_bih[r] + enc1_bhh[r]
__global__ void prep_wc(const float* __restrict__ e1Wih,
                        const float* __restrict__ encW,   // [512][34]
                        const float* __restrict__ encb,   // [512]
                        const float* __restrict__ e1bih,
                        const float* __restrict__ e1bhh)
{
    int n = blockIdx.x;                     // 0..2047
    int r = (n & 3) * 512 + (n >> 2);
    __shared__ float wr[512];
    for (int e = threadIdx.x; e < 512; e += blockDim.x)
        wr[e] = e1Wih[(long)r * 512 + e];
    __syncthreads();
    int t = threadIdx.x;
    if (t < 34) {
        float acc = 0.f;
        for (int e = 0; e < 512; e++)
            acc = fmaf(wr[e], encW[e * 34 + t], acc);
        g_Wt1[(long)(512 + t) * 2048 + n] = acc;
    } else if (t == 34) {
        float acc = e1bih[r] + e1bhh[r];
        for (int e = 0; e < 512; e++)
            acc = fmaf(wr[e], encb[e], acc);
        g_b1[n] = acc;
    } else if (t >= 35 && t < 49) {
        g_Wt1[(long)(546 + (t - 35)) * 2048 + n] = 0.f;   // zero pad rows
    }
}

// ---------------- zero initial state ----------------
__global__ void zero_state() {
    long i = (long)blockIdx.x * blockDim.x + threadIdx.x;
    if (i < (long)BE) {
        g_h1a[i] = 0.f; g_c1[i] = 0.f; g_h2a[i] = 0.f; g_c2[i] = 0.f;
    }
}

// ---------------- fused LSTM cell step: GEMM (gates) + elementwise ----------------
// gates[b][n] = sum_{k<K0} A0[b][k]*Wt[k][n] + sum_{K0<=k<Ktot} A1[b][k-K0]*Wt[k][n] + bias[n]
// N = 2048 fixed (gate-interleaved), M = 2048 fixed.
__global__ void __launch_bounds__(256, 2)
lstm_step(const float* __restrict__ A0, int lda0,
          const float* __restrict__ A1, int lda1,
          int K0, int Ktot,
          const float* __restrict__ Wt,
          const float* __restrict__ bias,
          const float* c_in,        // may alias c_out (in-place safe per-thread)
          float* h_out,
          float* c_out)
{
    __shared__ float As[16][132];
    __shared__ float Bs[16][128];

    const int tid = threadIdx.x;
    const int tx = tid & 15, ty = tid >> 4;
    const int n0 = blockIdx.x * 128;
    const int m0 = blockIdx.y * 128;

    const int a_m = tid >> 2;          // 0..63
    const int a_k = (tid & 3) << 2;    // 0,4,8,12
    const int b_k = tid >> 5;          // 0..7
    const int b_n = (tid & 31) << 2;   // 0..124

    const bool a1vec = (A1 != nullptr) && ((((uintptr_t)A1) & 15) == 0) && ((lda1 & 3) == 0);

    float acc[8][8];
#pragma unroll
    for (int i = 0; i < 8; i++)
#pragma unroll
        for (int j = 0; j < 8; j++) acc[i][j] = 0.f;

    for (int kk = 0; kk < Ktot; kk += 16) {
        // ---- load A tile (transposed into As[k][m]) ----
        if (kk + 16 <= K0) {
#pragma unroll
            for (int h = 0; h < 2; h++) {
                int m = a_m + h * 64;
                float4 v = *(const float4*)(A0 + (size_t)(m0 + m) * lda0 + kk + a_k);
                As[a_k + 0][m] = v.x; As[a_k + 1][m] = v.y;
                As[a_k + 2][m] = v.z; As[a_k + 3][m] = v.w;
            }
        } else if (a1vec && kk >= K0 && kk + 16 <= Ktot) {
#pragma unroll
            for (int h = 0; h < 2; h++) {
                int m = a_m + h * 64;
                float4 v = *(const float4*)(A1 + (size_t)(m0 + m) * lda1 + (kk - K0) + a_k);
                As[a_k + 0][m] = v.x; As[a_k + 1][m] = v.y;
                As[a_k + 2][m] = v.z; As[a_k + 3][m] = v.w;
            }
        } else {
#pragma unroll
            for (int h = 0; h < 2; h++) {
                int m = a_m + h * 64;
#pragma unroll
                for (int j = 0; j < 4; j++) {
                    int k = kk + a_k + j;
                    float v = 0.f;
                    if (k < K0)        v = A0[(size_t)(m0 + m) * lda0 + k];
                    else if (k < Ktot) v = A1[(size_t)(m0 + m) * lda1 + (k - K0)];
                    As[a_k + j][m] = v;
                }
            }
        }
        // ---- load B tile (Wt is k-major [k][2048]) ----
#pragma unroll
        for (int h = 0; h < 2; h++) {
            int k = kk + b_k + h * 8;
            float4 v = make_float4(0.f, 0.f, 0.f, 0.f);
            if (k < Ktot) v = *(const float4*)(Wt + (size_t)k * 2048 + n0 + b_n);
            *(float4*)&Bs[b_k + h * 8][b_n] = v;
        }
        __syncthreads();

        // ---- 8x8 outer products ----
#pragma unroll
        for (int k = 0; k < 16; k++) {
            float ar[8], br[8];
            *(float4*)&ar[0] = *(const float4*)&As[k][ty * 4];
            *(float4*)&ar[4] = *(const float4*)&As[k][ty * 4 + 64];
            *(float4*)&br[0] = *(const float4*)&Bs[k][tx * 4];
            *(float4*)&br[4] = *(const float4*)&Bs[k][tx * 4 + 64];
#pragma unroll
            for (int i = 0; i < 8; i++)
#pragma unroll
                for (int j = 0; j < 8; j++)
                    acc[i][j] = fmaf(ar[i], br[j], acc[i][j]);
        }
        __syncthreads();
    }

    // ---- fused LSTM epilogue: each 4-col group is a complete (i,f,g,o) quad ----
    const int col0 = n0 + tx * 4;
    const float4 bb0 = *(const float4*)&bias[col0];
    const float4 bb1 = *(const float4*)&bias[col0 + 64];
    const int e0 = col0 >> 2;
    const int e1 = (col0 + 64) >> 2;

#pragma unroll
    for (int i = 0; i < 8; i++) {
        const int m = m0 + ty * 4 + ((i < 4) ? i : (60 + i));
        {
            float cn = sigmoidf_(acc[i][1] + bb0.y) * c_in[(size_t)m * EE + e0]
                     + sigmoidf_(acc[i][0] + bb0.x) * tanhf_(acc[i][2] + bb0.z);
            float hn = sigmoidf_(acc[i][3] + bb0.w) * tanhf_(cn);
            c_out[(size_t)m * EE + e0] = cn;
            h_out[(size_t)m * EE + e0] = hn;
        }
        {
            float cn = sigmoidf_(acc[i][5] + bb1.y) * c_in[(size_t)m * EE + e1]
                     + sigmoidf_(acc[i][4] + bb1.x) * tanhf_(acc[i][6] + bb1.z);
            float hn = sigmoidf_(acc[i][7] + bb1.w) * tanhf_(cn);
            c_out[(size_t)m * EE + e1] = cn;
            h_out[(size_t)m * EE + e1] = hn;
        }
    }
}

// ---------------- final output linear: preds @ dec_lin_W^T + b ----------------
__global__ void final_linear(const float* __restrict__ preds,
                             const float* __restrict__ W,   // [34][512]
                             const float* __restrict__ bias,
                             float* __restrict__ out)
{
    int bf = blockIdx.x;            // b*FUT + f
    int f = bf % FUT;
    int b = bf / FUT;
    __shared__ float row[512];
    const float* src = preds + ((size_t)f * BB + b) * EE;
    for (int i = threadIdx.x; i < 512; i += blockDim.x) row[i] = src[i];
    __syncthreads();
    int p = threadIdx.x;
    if (p < POSE) {
        const float* w = W + (size_t)p * 512;
        float acc = bias[p];
        for (int e = 0; e < 512; e++) acc = fmaf(row[e], w[e], acc);
        out[(size_t)b * (FUT * POSE) + f * POSE + p] = acc;
    }
}

// ---------------- launch ----------------
extern "C" void kernel_launch(void* const* d_in, const int* in_sizes, int n_in,
                              void* d_out, int out_size)
{
    (void)in_sizes; (void)n_in; (void)out_size;
    const float* x     = (const float*)d_in[0];
    const float* encW  = (const float*)d_in[1];
    const float* encb  = (const float*)d_in[2];
    const float* e1Wih = (const float*)d_in[3];
    const float* e1Whh = (const float*)d_in[4];
    const float* e1bih = (const float*)d_in[5];
    const float* e1bhh = (const float*)d_in[6];
    const float* e2Wih = (const float*)d_in[7];
    const float* e2Whh = (const float*)d_in[8];
    const float* e2bih = (const float*)d_in[9];
    const float* e2bhh = (const float*)d_in[10];
    const float* d1Wih = (const float*)d_in[11];
    const float* d1Whh = (const float*)d_in[12];
    const float* d1bih = (const float*)d_in[13];
    const float* d1bhh = (const float*)d_in[14];
    const float* dW    = (const float*)d_in[15];
    const float* db    = (const float*)d_in[16];
    float* out = (float*)d_out;

    float *h1a, *h1b, *c1, *h2a, *h2b, *c2;
    float *Wt1, *Wt2, *WtD1, *WtDr, *b1, *b2, *bd, *preds;
    cudaGetSymbolAddress((void**)&h1a,  g_h1a);
    cudaGetSymbolAddress((void**)&h1b,  g_h1b);
    cudaGetSymbolAddress((void**)&c1,   g_c1);
    cudaGetSymbolAddress((void**)&h2a,  g_h2a);
    cudaGetSymbolAddress((void**)&h2b,  g_h2b);
    cudaGetSymbolAddress((void**)&c2,   g_c2);
    cudaGetSymbolAddress((void**)&Wt1,  g_Wt1);
    cudaGetSymbolAddress((void**)&Wt2,  g_Wt2);
    cudaGetSymbolAddress((void**)&WtD1, g_WtD1);
    cudaGetSymbolAddress((void**)&WtDr, g_WtDr);
    cudaGetSymbolAddress((void**)&b1,   g_b1);
    cudaGetSymbolAddress((void**)&b2,   g_b2);
    cudaGetSymbolAddress((void**)&bd,   g_bd);
    cudaGetSymbolAddress((void**)&preds, g_preds);

    prep_transpose<<<(2560 * 2048 + 255) / 256, 256>>>(e1Whh, e2Wih, e2Whh, d1Wih, d1Whh,
                                                       e2bih, e2bhh, d1bih, d1bhh);
    prep_wc<<<2048, 64>>>(e1Wih, encW, encb, e1bih, e1bhh);
    zero_state<<<BE / 256, 256>>>();

    dim3 grid(16, 16);
    for (int t = 0; t < TT; t++) {
        float* h1_in  = (t & 1) ? h1b : h1a;
        float* h1_out = (t & 1) ? h1a : h1b;
        // cell 1: gates = h1@Whh^T + x_t@Wc^T + b1   (K = 512 + 34)
        lstm_step<<<grid, 256>>>(h1_in, EE, x + (size_t)t * POSE, TT * POSE,
                                 512, 546, Wt1, b1, c1, h1_out, c1);
        float* h2_in  = (t & 1) ? h2b : h2a;
        float* h2_out = (t & 1) ? h2a : h2b;
        // cell 2: gates = h1_new@W2ih^T + h2@W2hh^T + b2   (K = 1024)
        lstm_step<<<grid, 256>>>(h1_out, EE, h2_in, EE,
                                 512, 1024, Wt2, b2, c2, h2_out, c2);
    }

    // decoder: step 0 input is zeros -> gates = h2@Whh^T + bd
    lstm_step<<<grid, 256>>>(h2a, EE, nullptr, 0,
                             512, 512, WtD1, bd, c2, preds, c2);
    // steps 1..9: out == h -> gates = h@(Wih+Whh)^T + bd
    for (int f = 1; f < FUT; f++) {
        lstm_step<<<grid, 256>>>(preds + (size_t)(f - 1) * BE, EE, nullptr, 0,
                                 512, 512, WtDr, bd, c2, preds + (size_t)f * BE, c2);
    }

    final_linear<<<BB * FUT, 64>>>(preds, dW, db, out);
}

// round 3
// speedup vs baseline: 1.0003x; 1.0003x over previous
#include <cuda_runtime.h>
#include <stdint.h>
#include <stddef.h>

#define BB 2048
#define TT 100
#define EE 512
#define POSE 34
#define FUT 10
#define BE (BB*EE)

// ---------------- scratch (static device globals; no allocation) ----------------
__device__ float g_h1a[BE], g_h1b[BE], g_c1[BE];
__device__ float g_h2a[BE], g_h2b[BE], g_c2[BE];
__device__ float g_Wt1[560*2048];    // [k][n] k-major: rows 0..511 = enc1_Whh^T (perm), 512..545 = Wc^T (perm), 546..559 = 0
__device__ float g_Wt2[1024*2048];   // rows 0..511 = enc2_Wih^T, 512..1023 = enc2_Whh^T (perm)
__device__ float g_WtD1[512*2048];   // dec first step: dec1_Whh^T (perm)
__device__ float g_WtDr[512*2048];   // dec steps >=1: (dec1_Wih+dec1_Whh)^T (perm)
__device__ float g_b1[2048], g_b2[2048], g_bd[2048];
__device__ float g_preds[FUT*BE];

// ---------------- math helpers ----------------
__device__ __forceinline__ float sigmoidf_(float x) {
    return __fdividef(1.f, 1.f + __expf(-x));
}
__device__ __forceinline__ float tanhf_(float x) {
    return 1.f - __fdividef(2.f, __expf(2.f * x) + 1.f);
}

// ---------------- prep: transpose + gate-interleave permute ----------------
// perm: output column n corresponds to original gate row r = (n%4)*512 + n/4
// so columns 4e..4e+3 are (i,f,g,o) for hidden index e.
__global__ void prep_transpose(
    const float* __restrict__ e1Whh,
    const float* __restrict__ e2Wih, const float* __restrict__ e2Whh,
    const float* __restrict__ d1Wih, const float* __restrict__ d1Whh,
    const float* __restrict__ e2bih, const float* __restrict__ e2bhh,
    const float* __restrict__ d1bih, const float* __restrict__ d1bhh)
{
    long idx = (long)blockIdx.x * blockDim.x + threadIdx.x;
    const long TOTAL = 2560L * 2048L;
    if (idx >= TOTAL) return;
    int n = (int)(idx & 2047);
    int krow = (int)(idx >> 11);            // 0..2559
    int r = (n & 3) * 512 + (n >> 2);       // original gate row

    if (krow < 512) {
        g_Wt1[(long)krow * 2048 + n] = e1Whh[(long)r * 512 + krow];
    } else if (krow < 1024) {
        int k = krow - 512;
        g_Wt2[(long)k * 2048 + n] = e2Wih[(long)r * 512 + k];
    } else if (krow < 1536) {
        int k = krow - 1024;
        g_Wt2[(long)(512 + k) * 2048 + n] = e2Whh[(long)r * 512 + k];
    } else if (krow < 2048) {
        int k = krow - 1536;
        g_WtD1[(long)k * 2048 + n] = d1Whh[(long)r * 512 + k];
    } else {
        int k = krow - 2048;
        g_WtDr[(long)k * 2048 + n] = d1Wih[(long)r * 512 + k] + d1Whh[(long)r * 512 + k];
    }
    if (krow == 0) {
        g_b2[n] = e2bih[r] + e2bhh[r];
        g_bd[n] = d1bih[r] + d1bhh[r];
    }
}

// ---------------- prep: fold enc_lin into enc1 input path ----------------
// Wc[r][p] = sum_e enc1_Wih[r][e] * enc_lin_W[e][p]  -> stored at Wt1 rows 512+p (perm cols)
// b1[n]    = enc1_Wih[r]·enc_lin_b + enc1_bih[r] + enc1_bhh[r]
__global__ void prep_wc(const float* __restrict__ e1Wih,
                        const float* __restrict__ encW,   // [512][34]
                        const float* __restrict__ encb,   // [512]
                        const float* __restrict__ e1bih,
                        const float* __restrict__ e1bhh)
{
    int n = blockIdx.x;                     // 0..2047
    int r = (n & 3) * 512 + (n >> 2);
    __shared__ float wr[512];
    for (int e = threadIdx.x; e < 512; e += blockDim.x)
        wr[e] = e1Wih[(long)r * 512 + e];
    __syncthreads();
    int t = threadIdx.x;
    if (t < 34) {
        float acc = 0.f;
        for (int e = 0; e < 512; e++)
            acc = fmaf(wr[e], encW[e * 34 + t], acc);
        g_Wt1[(long)(512 + t) * 2048 + n] = acc;
    } else if (t == 34) {
        float acc = e1bih[r] + e1bhh[r];
        for (int e = 0; e < 512; e++)
            acc = fmaf(wr[e], encb[e], acc);
        g_b1[n] = acc;
    } else if (t >= 35 && t < 49) {
        g_Wt1[(long)(546 + (t - 35)) * 2048 + n] = 0.f;   // zero pad rows
    }
}

// ---------------- zero initial state ----------------
__global__ void zero_state() {
    long i = (long)blockIdx.x * blockDim.x + threadIdx.x;
    if (i < (long)BE) {
        g_h1a[i] = 0.f; g_c1[i] = 0.f; g_h2a[i] = 0.f; g_c2[i] = 0.f;
    }
}

// ---------------- fused LSTM cell step: GEMM (gates) + elementwise ----------------
// gates[b][n] = sum_{k<K0} A0[b][k]*Wt[k][n] + sum_{K0<=k<Ktot} A1[b][k-K0]*Wt[k][n] + bias[n]
// N = 2048 fixed (gate-interleaved), M = 2048 fixed.
__global__ void __launch_bounds__(256, 2)
lstm_step(const float* __restrict__ A0, int lda0,
          const float* __restrict__ A1, int lda1,
          int K0, int Ktot,
          const float* __restrict__ Wt,
          const float* __restrict__ bias,
          const float* c_in,        // may alias c_out (in-place safe per-thread)
          float* h_out,
          float* c_out)
{
    __shared__ float As[16][132];
    __shared__ float Bs[16][128];

    const int tid = threadIdx.x;
    const int tx = tid & 15, ty = tid >> 4;
    const int n0 = blockIdx.x * 128;
    const int m0 = blockIdx.y * 128;

    const int a_m = tid >> 2;          // 0..63
    const int a_k = (tid & 3) << 2;    // 0,4,8,12
    const int b_k = tid >> 5;          // 0..7
    const int b_n = (tid & 31) << 2;   // 0..124

    const bool a1vec = (A1 != nullptr) && ((((uintptr_t)A1) & 15) == 0) && ((lda1 & 3) == 0);

    float acc[8][8];
#pragma unroll
    for (int i = 0; i < 8; i++)
#pragma unroll
        for (int j = 0; j < 8; j++) acc[i][j] = 0.f;

    for (int kk = 0; kk < Ktot; kk += 16) {
        // ---- load A tile (transposed into As[k][m]) ----
        if (kk + 16 <= K0) {
#pragma unroll
            for (int h = 0; h < 2; h++) {
                int m = a_m + h * 64;
                float4 v = *(const float4*)(A0 + (size_t)(m0 + m) * lda0 + kk + a_k);
                As[a_k + 0][m] = v.x; As[a_k + 1][m] = v.y;
                As[a_k + 2][m] = v.z; As[a_k + 3][m] = v.w;
            }
        } else if (a1vec && kk >= K0 && kk + 16 <= Ktot) {
#pragma unroll
            for (int h = 0; h < 2; h++) {
                int m = a_m + h * 64;
                float4 v = *(const float4*)(A1 + (size_t)(m0 + m) * lda1 + (kk - K0) + a_k);
                As[a_k + 0][m] = v.x; As[a_k + 1][m] = v.y;
                As[a_k + 2][m] = v.z; As[a_k + 3][m] = v.w;
            }
        } else {
#pragma unroll
            for (int h = 0; h < 2; h++) {
                int m = a_m + h * 64;
#pragma unroll
                for (int j = 0; j < 4; j++) {
                    int k = kk + a_k + j;
                    float v = 0.f;
                    if (k < K0)        v = A0[(size_t)(m0 + m) * lda0 + k];
                    else if (k < Ktot) v = A1[(size_t)(m0 + m) * lda1 + (k - K0)];
                    As[a_k + j][m] = v;
                }
            }
        }
        // ---- load B tile (Wt is k-major [k][2048]) ----
#pragma unroll
        for (int h = 0; h < 2; h++) {
            int k = kk + b_k + h * 8;
            float4 v = make_float4(0.f, 0.f, 0.f, 0.f);
            if (k < Ktot) v = *(const float4*)(Wt + (size_t)k * 2048 + n0 + b_n);
            *(float4*)&Bs[b_k + h * 8][b_n] = v;
        }
        __syncthreads();

        // ---- 8x8 outer products ----
#pragma unroll
        for (int k = 0; k < 16; k++) {
            float ar[8], br[8];
            *(float4*)&ar[0] = *(const float4*)&As[k][ty * 4];
            *(float4*)&ar[4] = *(const float4*)&As[k][ty * 4 + 64];
            *(float4*)&br[0] = *(const float4*)&Bs[k][tx * 4];
            *(float4*)&br[4] = *(const float4*)&Bs[k][tx * 4 + 64];
#pragma unroll
            for (int i = 0; i < 8; i++)
#pragma unroll
                for (int j = 0; j < 8; j++)
                    acc[i][j] = fmaf(ar[i], br[j], acc[i][j]);
        }
        __syncthreads();
    }

    // ---- fused LSTM epilogue: each 4-col group is a complete (i,f,g,o) quad ----
    const int col0 = n0 + tx * 4;
    const float4 bb0 = *(const float4*)&bias[col0];
    const float4 bb1 = *(const float4*)&bias[col0 + 64];
    const int e0 = col0 >> 2;
    const int e1 = (col0 + 64) >> 2;

#pragma unroll
    for (int i = 0; i < 8; i++) {
        const int m = m0 + ty * 4 + ((i < 4) ? i : (60 + i));
        {
            float cn = sigmoidf_(acc[i][1] + bb0.y) * c_in[(size_t)m * EE + e0]
                     + sigmoidf_(acc[i][0] + bb0.x) * tanhf_(acc[i][2] + bb0.z);
            float hn = sigmoidf_(acc[i][3] + bb0.w) * tanhf_(cn);
            c_out[(size_t)m * EE + e0] = cn;
            h_out[(size_t)m * EE + e0] = hn;
        }
        {
            float cn = sigmoidf_(acc[i][5] + bb1.y) * c_in[(size_t)m * EE + e1]
                     + sigmoidf_(acc[i][4] + bb1.x) * tanhf_(acc[i][6] + bb1.z);
            float hn = sigmoidf_(acc[i][7] + bb1.w) * tanhf_(cn);
            c_out[(size_t)m * EE + e1] = cn;
            h_out[(size_t)m * EE + e1] = hn;
        }
    }
}

// ---------------- final output linear: preds @ dec_lin_W^T + b ----------------
__global__ void final_linear(const float* __restrict__ preds,
                             const float* __restrict__ W,   // [34][512]
                             const float* __restrict__ bias,
                             float* __restrict__ out)
{
    int bf = blockIdx.x;            // b*FUT + f
    int f = bf % FUT;
    int b = bf / FUT;
    __shared__ float row[512];
    const float* src = preds + ((size_t)f * BB + b) * EE;
    for (int i = threadIdx.x; i < 512; i += blockDim.x) row[i] = src[i];
    __syncthreads();
    int p = threadIdx.x;
    if (p < POSE) {
        const float* w = W + (size_t)p * 512;
        float acc = bias[p];
        for (int e = 0; e < 512; e++) acc = fmaf(row[e], w[e], acc);
        out[(size_t)b * (FUT * POSE) + f * POSE + p] = acc;
    }
}

// ---------------- launch ----------------
extern "C" void kernel_launch(void* const* d_in, const int* in_sizes, int n_in,
                              void* d_out, int out_size)
{
    (void)in_sizes; (void)n_in; (void)out_size;
    const float* x     = (const float*)d_in[0];
    const float* encW  = (const float*)d_in[1];
    const float* encb  = (const float*)d_in[2];
    const float* e1Wih = (const float*)d_in[3];
    const float* e1Whh = (const float*)d_in[4];
    const float* e1bih = (const float*)d_in[5];
    const float* e1bhh = (const float*)d_in[6];
    const float* e2Wih = (const float*)d_in[7];
    const float* e2Whh = (const float*)d_in[8];
    const float* e2bih = (const float*)d_in[9];
    const float* e2bhh = (const float*)d_in[10];
    const float* d1Wih = (const float*)d_in[11];
    const float* d1Whh = (const float*)d_in[12];
    const float* d1bih = (const float*)d_in[13];
    const float* d1bhh = (const float*)d_in[14];
    const float* dW    = (const float*)d_in[15];
    const float* db    = (const float*)d_in[16];
    float* out = (float*)d_out;

    float *h1a, *h1b, *c1, *h2a, *h2b, *c2;
    float *Wt1, *Wt2, *WtD1, *WtDr, *b1, *b2, *bd, *preds;
    cudaGetSymbolAddress((void**)&h1a,  g_h1a);
    cudaGetSymbolAddress((void**)&h1b,  g_h1b);
    cudaGetSymbolAddress((void**)&c1,   g_c1);
    cudaGetSymbolAddress((void**)&h2a,  g_h2a);
    cudaGetSymbolAddress((void**)&h2b,  g_h2b);
    cudaGetSymbolAddress((void**)&c2,   g_c2);
    cudaGetSymbolAddress((void**)&Wt1,  g_Wt1);
    cudaGetSymbolAddress((void**)&Wt2,  g_Wt2);
    cudaGetSymbolAddress((void**)&WtD1, g_WtD1);
    cudaGetSymbolAddress((void**)&WtDr, g_WtDr);
    cudaGetSymbolAddress((void**)&b1,   g_b1);
    cudaGetSymbolAddress((void**)&b2,   g_b2);
    cudaGetSymbolAddress((void**)&bd,   g_bd);
    cudaGetSymbolAddress((void**)&preds, g_preds);

    prep_transpose<<<(2560 * 2048 + 255) / 256, 256>>>(e1Whh, e2Wih, e2Whh, d1Wih, d1Whh,
                                                       e2bih, e2bhh, d1bih, d1bhh);
    prep_wc<<<2048, 64>>>(e1Wih, encW, encb, e1bih, e1bhh);
    zero_state<<<BE / 256, 256>>>();

    dim3 grid(16, 16);
    for (int t = 0; t < TT; t++) {
        float* h1_in  = (t & 1) ? h1b : h1a;
        float* h1_out = (t & 1) ? h1a : h1b;
        // cell 1: gates = h1@Whh^T + x_t@Wc^T + b1   (K = 512 + 34)
        lstm_step<<<grid, 256>>>(h1_in, EE, x + (size_t)t * POSE, TT * POSE,
                                 512, 546, Wt1, b1, c1, h1_out, c1);
        float* h2_in  = (t & 1) ? h2b : h2a;
        float* h2_out = (t & 1) ? h2a : h2b;
        // cell 2: gates = h1_new@W2ih^T + h2@W2hh^T + b2   (K = 1024)
        lstm_step<<<grid, 256>>>(h1_out, EE, h2_in, EE,
                                 512, 1024, Wt2, b2, c2, h2_out, c2);
    }

    // decoder: step 0 input is zeros -> gates = h2@Whh^T + bd
    lstm_step<<<grid, 256>>>(h2a, EE, nullptr, 0,
                             512, 512, WtD1, bd, c2, preds, c2);
    // steps 1..9: out == h -> gates = h@(Wih+Whh)^T + bd
    for (int f = 1; f < FUT; f++) {
        lstm_step<<<grid, 256>>>(preds + (size_t)(f - 1) * BE, EE, nullptr, 0,
                                 512, 512, WtDr, bd, c2, preds + (size_t)f * BE, c2);
    }

    final_linear<<<BB * FUT, 64>>>(preds, dW, db, out);
}

// round 5
// speedup vs baseline: 1.4257x; 1.4253x over previous
#include <cuda_runtime.h>
#include <cuda_bf16.h>
#include <stdint.h>
#include <stddef.h>

#define BB 2048
#define TT 100
#define EE 512
#define POSE 34
#define FUT 10
#define BE (BB*EE)

#define K1 576        // cell1: 512 (h1) + 64 (x slab: 34 real + pad)
#define K2 1024       // cell2: 512 (h1_new) + 512 (h2)
#define KD 512        // decoder

// SMEM pipeline: 3 stages x 32KB (Ah 8K | Al 8K | Bh 8K | Bl 8K)
#define STAGE_BYTES 32768
#define OFF_AH 0
#define OFF_AL 8192
#define OFF_BH 16384
#define OFF_BL 24576
#define SMEM_TOTAL (3*STAGE_BYTES)

// ---------------- device globals (no allocation allowed) ----------------
__device__ __align__(16) __nv_bfloat16 g_h1h[2][BE], g_h1l[2][BE];
__device__ __align__(16) __nv_bfloat16 g_h2h[2][BE], g_h2l[2][BE];
__device__ __align__(16) __nv_bfloat16 g_dhh[2][BE], g_dhl[2][BE];
__device__ __align__(16) float g_c1[BE], g_c2[BE];
__device__ __align__(16) __nv_bfloat16 g_W1h[2048*K1], g_W1l[2048*K1];
__device__ __align__(16) __nv_bfloat16 g_W2h[2048*K2], g_W2l[2048*K2];
__device__ __align__(16) __nv_bfloat16 g_WD1h[2048*KD], g_WD1l[2048*KD];
__device__ __align__(16) __nv_bfloat16 g_WDrh[2048*KD], g_WDrl[2048*KD];
__device__ __align__(16) __nv_bfloat16 g_xh[(size_t)TT*BB*64], g_xl[(size_t)TT*BB*64];
__device__ __align__(16) float g_b1[2048], g_b2[2048], g_bd[2048];
__device__ __align__(16) float g_preds[(size_t)FUT*BE];

// ---------------- helpers ----------------
__device__ __forceinline__ float sigmoidf_(float x) { return __fdividef(1.f, 1.f + __expf(-x)); }
__device__ __forceinline__ float tanhf_(float x)    { return 1.f - __fdividef(2.f, __expf(2.f*x) + 1.f); }

__device__ __forceinline__ void split_bf16(float v, __nv_bfloat16& hi, __nv_bfloat16& lo) {
    hi = __float2bfloat16(v);
    lo = __float2bfloat16(v - __bfloat162float(hi));
}

__device__ __forceinline__ uint32_t smem_u32(const void* p) {
    uint32_t a;
    asm("{ .reg .u64 t; cvta.to.shared.u64 t, %1; cvt.u32.u64 %0, t; }" : "=r"(a) : "l"(p));
    return a;
}

// Interleaved tile layout: tile is 128 rows x 32 k (bf16). Physical: 64 rows x 128B.
// element (row, kk): physrow r = row>>1, chunk = ((row&1)*4 + (kk>>3)) ^ (r&7),
// byte = r*128 + chunk*16 + (kk&7)*2.  Conflict-free for cp.async STS and ldmatrix.
__device__ __forceinline__ uint32_t tile_addr(uint32_t base, int row, int kk) {
    int r = row >> 1;
    int c = (((row & 1) << 2) + (kk >> 3)) ^ (r & 7);
    return base + (uint32_t)(r * 128 + c * 16 + (kk & 7) * 2);
}

__device__ __forceinline__ void cp16(uint32_t s, const void* g) {
    asm volatile("cp.async.cg.shared.global [%0], [%1], 16;" :: "r"(s), "l"(g));
}
__device__ __forceinline__ void cp_commit() { asm volatile("cp.async.commit_group;"); }
__device__ __forceinline__ void cp_wait2()  { asm volatile("cp.async.wait_group 2;"); }

__device__ __forceinline__ void ldsm4(uint32_t* d, uint32_t a) {
    asm volatile("ldmatrix.sync.aligned.m8n8.x4.shared.b16 {%0,%1,%2,%3}, [%4];"
        : "=r"(d[0]), "=r"(d[1]), "=r"(d[2]), "=r"(d[3]) : "r"(a));
}
__device__ __forceinline__ void mma_bf16(float* d, const uint32_t* a, const uint32_t* b) {
    asm volatile("mma.sync.aligned.m16n8k16.row.col.f32.bf16.bf16.f32 "
        "{%0,%1,%2,%3}, {%4,%5,%6,%7}, {%8,%9}, {%0,%1,%2,%3};"
        : "+f"(d[0]), "+f"(d[1]), "+f"(d[2]), "+f"(d[3])
        : "r"(a[0]), "r"(a[1]), "r"(a[2]), "r"(a[3]), "r"(b[0]), "r"(b[1]));
}

// ============ fused mma.sync LSTM step ============
// gates[m][n] = sum_k A[m][k]*W[n][k] + bias[n];  A = concat(A0[0:K0], A1[K0:Ktot])
// n gate-interleaved: cols 4e..4e+3 = (i,f,g,o) of hidden unit e.
__global__ void __launch_bounds__(256, 2)
lstm_mma_step(const __nv_bfloat16* __restrict__ A0h, const __nv_bfloat16* __restrict__ A0l, int lda0,
              const __nv_bfloat16* __restrict__ A1h, const __nv_bfloat16* __restrict__ A1l, int lda1,
              int K0, int Ktot,
              const __nv_bfloat16* __restrict__ Wh, const __nv_bfloat16* __restrict__ Wl, int ldw,
              const float* __restrict__ bias,
              float* __restrict__ c_inout,
              __nv_bfloat16* __restrict__ Hh, __nv_bfloat16* __restrict__ Hl,
              float* __restrict__ Hf)
{
    extern __shared__ char smem[];
    const uint32_t sbase = smem_u32(smem);
    const int tid  = threadIdx.x;
    const int lane = tid & 31;
    const int warp = tid >> 5;
    const int wm = warp >> 2;          // 0..1
    const int wn = warp & 3;           // 0..3
    const int n0 = blockIdx.x * 128;
    const int m0 = blockIdx.y * 128;

    const int NC = Ktot >> 5;          // 32-k stages

    // per-thread load indices: 2 chunks per region per phase
    const int ch0 = tid, ch1 = tid + 256;

    // ---- stage issue ----
    auto issue = [&](int st) {
        const int kstW = st << 5;
        int kstA = kstW;
        const char *pAh = (const char*)A0h, *pAl = (const char*)A0l;
        int lda = lda0;
        if (kstA >= K0) { pAh = (const char*)A1h; pAl = (const char*)A1l; lda = lda1; kstA -= K0; }
        const uint32_t sb = sbase + (uint32_t)((st % 3) * STAGE_BYTES);
#pragma unroll
        for (int p = 0; p < 2; p++) {
            const int ch = p ? ch1 : ch0;
            const int row = ch >> 2, c = ch & 3;
            // A
            {
                uint32_t so = tile_addr(sb + OFF_AH, row, c * 8);
                const char* ga = pAh + ((size_t)(m0 + row) * lda + kstA + c * 8) * 2;
                const char* gl = pAl + ((size_t)(m0 + row) * lda + kstA + c * 8) * 2;
                cp16(so, ga);
                cp16(so + (OFF_AL - OFF_AH), gl);
            }
            // B
            {
                uint32_t so = tile_addr(sb + OFF_BH, row, c * 8);
                const char* gb = (const char*)Wh + ((size_t)(n0 + row) * ldw + kstW + c * 8) * 2;
                const char* gl = (const char*)Wl + ((size_t)(n0 + row) * ldw + kstW + c * 8) * 2;
                cp16(so, gb);
                cp16(so + (OFF_BL - OFF_BH), gl);
            }
        }
        cp_commit();
    };

    issue(0);
    issue(1);

    float acc[16][4];
#pragma unroll
    for (int i = 0; i < 16; i++)
#pragma unroll
        for (int j = 0; j < 4; j++) acc[i][j] = 0.f;

    // lane-derived ldmatrix row/col offsets
    const int laA_r = lane & 15;            // row within m16
    const int laA_k = (lane >> 4) * 8;      // k half
    const int laB_r = (lane & 7) + ((lane >> 4) & 1) * 8;   // n within 16
    const int laB_k = ((lane >> 3) & 1) * 8;                // k half

    for (int cs = 0; cs < NC; cs++) {
        if (cs + 2 < NC) issue(cs + 2); else cp_commit();
        cp_wait2();
        __syncthreads();

        const uint32_t sb = sbase + (uint32_t)((cs % 3) * STAGE_BYTES);

#pragma unroll
        for (int h = 0; h < 2; h++) {
            const int kk0 = h * 16;
            uint32_t Ah[4][4], Al[4][4], Bh[8], Bl[8];
            // A hi
#pragma unroll
            for (int i = 0; i < 4; i++)
                ldsm4(Ah[i], tile_addr(sb + OFF_AH, wm * 64 + i * 16 + laA_r, kk0 + laA_k));
            // B hi (two x4: n 0..15 and 16..31 of this warp's 32)
            ldsm4(&Bh[0], tile_addr(sb + OFF_BH, wn * 32 + laB_r,      kk0 + laB_k));
            ldsm4(&Bh[4], tile_addr(sb + OFF_BH, wn * 32 + 16 + laB_r, kk0 + laB_k));
#pragma unroll
            for (int i = 0; i < 4; i++)
#pragma unroll
                for (int j = 0; j < 4; j++)
                    mma_bf16(acc[i * 4 + j], Ah[i], &Bh[j * 2]);
            // B lo; hi*lo  (Ah still live)
            ldsm4(&Bl[0], tile_addr(sb + OFF_BL, wn * 32 + laB_r,      kk0 + laB_k));
            ldsm4(&Bl[4], tile_addr(sb + OFF_BL, wn * 32 + 16 + laB_r, kk0 + laB_k));
#pragma unroll
            for (int i = 0; i < 4; i++)
#pragma unroll
                for (int j = 0; j < 4; j++)
                    mma_bf16(acc[i * 4 + j], Ah[i], &Bl[j * 2]);
            // A lo; lo*hi
#pragma unroll
            for (int i = 0; i < 4; i++)
                ldsm4(Al[i], tile_addr(sb + OFF_AL, wm * 64 + i * 16 + laA_r, kk0 + laA_k));
#pragma unroll
            for (int i = 0; i < 4; i++)
#pragma unroll
                for (int j = 0; j < 4; j++)
                    mma_bf16(acc[i * 4 + j], Al[i], &Bh[j * 2]);
        }
        __syncthreads();
    }

    // ---- fused LSTM epilogue (register-resident) ----
    // acc tile (i,j): thread lane covers rows (lane>>2)+{0,8}, col pair (lane&3)*2+{0,1}.
    // pair (lane, lane^1) jointly owns a gate quad; shfl_xor(1) assembles it.
    const int pairpos = lane & 1;
    const int rbase = lane >> 2;
    const int elocal = (lane >> 1) & 1;

#pragma unroll
    for (int i = 0; i < 4; i++) {
#pragma unroll
        for (int j = 0; j < 4; j++) {
            float* a = acc[i * 4 + j];
            float r0 = __shfl_xor_sync(0xffffffffu, a[0], 1);
            float r1 = __shfl_xor_sync(0xffffffffu, a[1], 1);
            float r2 = __shfl_xor_sync(0xffffffffu, a[2], 1);
            float r3 = __shfl_xor_sync(0xffffffffu, a[3], 1);
            float gi, gf, gg, go;
            if (pairpos == 0) { gi = a[0]; gf = a[1]; gg = r0; go = r1; }   // row rbase
            else              { gi = r2;  gf = r3;  gg = a[2]; go = a[3]; } // row rbase+8
            const int m = m0 + wm * 64 + i * 16 + rbase + pairpos * 8;
            const int e = ((n0 + wn * 32 + j * 8) >> 2) + elocal;

            const float4 bq = ((const float4*)bias)[e];
            gi += bq.x; gf += bq.y; gg += bq.z; go += bq.w;

            const size_t off = (size_t)m * EE + e;
            const float co = c_inout[off];
            const float cn = sigmoidf_(gf) * co + sigmoidf_(gi) * tanhf_(gg);
            const float hn = sigmoidf_(go) * tanhf_(cn);
            c_inout[off] = cn;
            __nv_bfloat16 hh, hl;
            split_bf16(hn, hh, hl);
            Hh[off] = hh;
            Hl[off] = hl;
            if (Hf) Hf[off] = hn;
        }
    }
}

// ============ prep kernels ============
// permuted gate col n -> original row r = (n%4)*512 + n/4  (quad (i,f,g,o) per hidden e)
__global__ void prep_weights(const float* __restrict__ e1Whh,
                             const float* __restrict__ e2Wih, const float* __restrict__ e2Whh,
                             const float* __restrict__ d1Wih, const float* __restrict__ d1Whh,
                             const float* __restrict__ e2bih, const float* __restrict__ e2bhh,
                             const float* __restrict__ d1bih, const float* __restrict__ d1bhh)
{
    int n = blockIdx.y;
    int kk = blockIdx.x * 256 + threadIdx.x;
    if (kk >= K1 + K2 + KD + KD) return;
    int r = (n & 3) * 512 + (n >> 2);
    float v; __nv_bfloat16 *ph, *pl; long o;
    if (kk < K1) {
        v = (kk < 512) ? e1Whh[(long)r * 512 + kk] : 0.f;   // 512..575 pad; 512..545 overwritten by prep_wc
        ph = g_W1h; pl = g_W1l; o = (long)n * K1 + kk;
    } else if (kk < K1 + K2) {
        int k = kk - K1;
        v = (k < 512) ? e2Wih[(long)r * 512 + k] : e2Whh[(long)r * 512 + (k - 512)];
        ph = g_W2h; pl = g_W2l; o = (long)n * K2 + k;
    } else if (kk < K1 + K2 + KD) {
        int k = kk - (K1 + K2);
        v = d1Whh[(long)r * 512 + k];
        ph = g_WD1h; pl = g_WD1l; o = (long)n * KD + k;
    } else {
        int k = kk - (K1 + K2 + KD);
        v = d1Wih[(long)r * 512 + k] + d1Whh[(long)r * 512 + k];
        ph = g_WDrh; pl = g_WDrl; o = (long)n * KD + k;
    }
    __nv_bfloat16 hi, lo;
    split_bf16(v, hi, lo);
    ph[o] = hi; pl[o] = lo;
    if (kk == 0) {
        g_b2[n] = e2bih[r] + e2bhh[r];
        g_bd[n] = d1bih[r] + d1bhh[r];
    }
}

// Wc = e1Wih @ enc_lin_W folded into W1 rows 512..545; b1 = e1Wih·enc_b + biases
__global__ void prep_wc(const float* __restrict__ e1Wih,
                        const float* __restrict__ encW, const float* __restrict__ encb,
                        const float* __restrict__ e1bih, const float* __restrict__ e1bhh)
{
    int n = blockIdx.x;
    int r = (n & 3) * 512 + (n >> 2);
    __shared__ float wr[512];
    for (int e = threadIdx.x; e < 512; e += blockDim.x) wr[e] = e1Wih[(long)r * 512 + e];
    __syncthreads();
    int t = threadIdx.x;
    if (t < POSE) {
        float acc = 0.f;
        for (int e = 0; e < 512; e++) acc = fmaf(wr[e], encW[e * POSE + t], acc);
        __nv_bfloat16 hi, lo;
        split_bf16(acc, hi, lo);
        g_W1h[(long)n * K1 + 512 + t] = hi;
        g_W1l[(long)n * K1 + 512 + t] = lo;
    } else if (t == POSE) {
        float acc = e1bih[r] + e1bhh[r];
        for (int e = 0; e < 512; e++) acc = fmaf(wr[e], encb[e], acc);
        g_b1[n] = acc;
    }
}

__global__ void prep_x(const float* __restrict__ x) {
    long idx = (long)blockIdx.x * 256 + threadIdx.x;
    if (idx >= (long)TT * BB * 64) return;
    int c = (int)(idx & 63);
    int b = (int)((idx >> 6) & (BB - 1));
    int t = (int)(idx >> 17);
    float v = (c < POSE) ? x[(long)b * (TT * POSE) + t * POSE + c] : 0.f;
    __nv_bfloat16 hi, lo;
    split_bf16(v, hi, lo);
    g_xh[idx] = hi; g_xl[idx] = lo;
}

__global__ void zero_init() {
    long i = (long)blockIdx.x * 256 + threadIdx.x;
    if (i < (long)BE) {
        __nv_bfloat16 z = __float2bfloat16(0.f);
        g_h1h[0][i] = z; g_h1l[0][i] = z;
        g_h2h[0][i] = z; g_h2l[0][i] = z;
        g_c1[i] = 0.f; g_c2[i] = 0.f;
    }
}

__global__ void final_linear(const float* __restrict__ preds,
                             const float* __restrict__ W, const float* __restrict__ bias,
                             float* __restrict__ out)
{
    int bf = blockIdx.x;
    int f = bf % FUT;
    int b = bf / FUT;
    __shared__ float row[512];
    const float* src = preds + ((size_t)f * BB + b) * EE;
    for (int i = threadIdx.x; i < 512; i += blockDim.x) row[i] = src[i];
    __syncthreads();
    int p = threadIdx.x;
    if (p < POSE) {
        const float* w = W + (size_t)p * 512;
        float acc = bias[p];
        for (int e = 0; e < 512; e++) acc = fmaf(row[e], w[e], acc);
        out[(size_t)b * (FUT * POSE) + f * POSE + p] = acc;
    }
}

// ============ launch ============
extern "C" void kernel_launch(void* const* d_in, const int* in_sizes, int n_in,
                              void* d_out, int out_size)
{
    (void)in_sizes; (void)n_in; (void)out_size;
    const float* x     = (const float*)d_in[0];
    const float* encW  = (const float*)d_in[1];
    const float* encb  = (const float*)d_in[2];
    const float* e1Wih = (const float*)d_in[3];
    const float* e1Whh = (const float*)d_in[4];
    const float* e1bih = (const float*)d_in[5];
    const float* e1bhh = (const float*)d_in[6];
    const float* e2Wih = (const float*)d_in[7];
    const float* e2Whh = (const float*)d_in[8];
    const float* e2bih = (const float*)d_in[9];
    const float* e2bhh = (const float*)d_in[10];
    const float* d1Wih = (const float*)d_in[11];
    const float* d1Whh = (const float*)d_in[12];
    const float* d1bih = (const float*)d_in[13];
    const float* d1bhh = (const float*)d_in[14];
    const float* dW    = (const float*)d_in[15];
    const float* db    = (const float*)d_in[16];
    float* out = (float*)d_out;

    __nv_bfloat16 *h1h, *h1l, *h2h, *h2l, *dhh, *dhl;
    __nv_bfloat16 *W1h, *W1l, *W2h, *W2l, *WD1h, *WD1l, *WDrh, *WDrl, *xh, *xl;
    float *c1, *c2, *b1, *b2, *bd, *preds;
    cudaGetSymbolAddress((void**)&h1h, g_h1h);  cudaGetSymbolAddress((void**)&h1l, g_h1l);
    cudaGetSymbolAddress((void**)&h2h, g_h2h);  cudaGetSymbolAddress((void**)&h2l, g_h2l);
    cudaGetSymbolAddress((void**)&dhh, g_dhh);  cudaGetSymbolAddress((void**)&dhl, g_dhl);
    cudaGetSymbolAddress((void**)&c1,  g_c1);   cudaGetSymbolAddress((void**)&c2,  g_c2);
    cudaGetSymbolAddress((void**)&W1h, g_W1h);  cudaGetSymbolAddress((void**)&W1l, g_W1l);
    cudaGetSymbolAddress((void**)&W2h, g_W2h);  cudaGetSymbolAddress((void**)&W2l, g_W2l);
    cudaGetSymbolAddress((void**)&WD1h, g_WD1h); cudaGetSymbolAddress((void**)&WD1l, g_WD1l);
    cudaGetSymbolAddress((void**)&WDrh, g_WDrh); cudaGetSymbolAddress((void**)&WDrl, g_WDrl);
    cudaGetSymbolAddress((void**)&xh,  g_xh);   cudaGetSymbolAddress((void**)&xl,  g_xl);
    cudaGetSymbolAddress((void**)&b1,  g_b1);   cudaGetSymbolAddress((void**)&b2,  g_b2);
    cudaGetSymbolAddress((void**)&bd,  g_bd);   cudaGetSymbolAddress((void**)&preds, g_preds);

    cudaFuncSetAttribute(lstm_mma_step, cudaFuncAttributeMaxDynamicSharedMemorySize, SMEM_TOTAL);

    prep_weights<<<dim3((K1 + K2 + 2 * KD + 255) / 256, 2048), 256>>>(
        e1Whh, e2Wih, e2Whh, d1Wih, d1Whh, e2bih, e2bhh, d1bih, d1bhh);
    prep_wc<<<2048, 64>>>(e1Wih, encW, encb, e1bih, e1bhh);
    prep_x<<<(int)(((long)TT * BB * 64 + 255) / 256), 256>>>(x);
    zero_init<<<(BE + 255) / 256, 256>>>();

    dim3 grid(16, 16);
    for (int t = 0; t < TT; t++) {
        int in = t & 1, ot = (t + 1) & 1;
        // cell 1: A = [h1 | x_t slab], K = 576
        lstm_mma_step<<<grid, 256, SMEM_TOTAL>>>(
            h1h + (size_t)in * BE, h1l + (size_t)in * BE, EE,
            xh + (size_t)t * BB * 64, xl + (size_t)t * BB * 64, 64,
            512, K1, W1h, W1l, K1, b1, c1,
            h1h + (size_t)ot * BE, h1l + (size_t)ot * BE, nullptr);
        // cell 2: A = [h1_new | h2], K = 1024
        lstm_mma_step<<<grid, 256, SMEM_TOTAL>>>(
            h1h + (size_t)ot * BE, h1l + (size_t)ot * BE, EE,
            h2h + (size_t)in * BE, h2l + (size_t)in * BE, EE,
            512, K2, W2h, W2l, K2, b2, c2,
            h2h + (size_t)ot * BE, h2l + (size_t)ot * BE, nullptr);
    }
    // encoder final h2/c2 in slot 0 (t=99 -> ot=0)

    // decoder step 0: input zeros -> gates = h2 @ Whh^T + bd
    lstm_mma_step<<<grid, 256, SMEM_TOTAL>>>(
        h2h, h2l, EE, nullptr, nullptr, 0,
        KD, KD, WD1h, WD1l, KD, bd, c2,
        dhh, dhl, preds);
    // steps 1..9: out == h -> gates = h @ (Wih+Whh)^T + bd
    for (int f = 1; f < FUT; f++) {
        int ip = (f - 1) & 1, op = f & 1;
        lstm_mma_step<<<grid, 256, SMEM_TOTAL>>>(
            dhh + (size_t)ip * BE, dhl + (size_t)ip * BE, EE, nullptr, nullptr, 0,
            KD, KD, WDrh, WDrl, KD, bd, c2,
            dhh + (size_t)op * BE, dhl + (size_t)op * BE, preds + (size_t)f * BE);
    }

    final_linear<<<BB * FUT, 64>>>(preds, dW, db, out);
}

// round 6
// speedup vs baseline: 2.0184x; 1.4157x over previous
#include <cuda_runtime.h>
#include <cuda_fp16.h>
#include <stdint.h>
#include <stddef.h>

#define BB 2048
#define TT 100
#define EE 512
#define POSE 34
#define FUT 10
#define BE (BB*EE)

#define K1 576        // cell1: 512 (h1) + 64 (x slab: 34 real + pad)
#define K2 1024       // cell2: 512 (h1_new) + 512 (h2)
#define KD 512        // decoder

#define WSCALE 256.0f
#define WSCALE_INV (1.0f/256.0f)

// SMEM pipeline: 4 stages x 24KB (A 8K | Bh 8K | Bl 8K)
#define STAGE_BYTES 24576
#define OFF_A  0
#define OFF_BH 8192
#define OFF_BL 16384
#define NSTAGE 4
#define SMEM_TOTAL (NSTAGE*STAGE_BYTES)

// ---------------- device globals (no allocation allowed) ----------------
__device__ __align__(16) __half g_h1[2][BE];
__device__ __align__(16) __half g_h2[2][BE];
__device__ __align__(16) __half g_dh[2][BE];
__device__ __align__(16) float g_c1[BE], g_c2[BE];
__device__ __align__(16) __half g_W1h[2048*K1], g_W1l[2048*K1];
__device__ __align__(16) __half g_W2h[2048*K2], g_W2l[2048*K2];
__device__ __align__(16) __half g_WD1h[2048*KD], g_WD1l[2048*KD];
__device__ __align__(16) __half g_WDrh[2048*KD], g_WDrl[2048*KD];
__device__ __align__(16) __half g_x[(size_t)TT*BB*64];
__device__ __align__(16) float g_b1[2048], g_b2[2048], g_bd[2048];
__device__ __align__(16) float g_preds[(size_t)FUT*BE];

// ---------------- helpers ----------------
__device__ __forceinline__ float sigmoidf_(float x) { return __fdividef(1.f, 1.f + __expf(-x)); }
__device__ __forceinline__ float tanhf_(float x)    { return 1.f - __fdividef(2.f, __expf(2.f*x) + 1.f); }

__device__ __forceinline__ void split_f16(float v, __half& hi, __half& lo) {
    hi = __float2half_rn(v);
    lo = __float2half_rn(v - __half2float(hi));
}

__device__ __forceinline__ uint32_t smem_u32(const void* p) {
    uint32_t a;
    asm("{ .reg .u64 t; cvta.to.shared.u64 t, %1; cvt.u32.u64 %0, t; }" : "=r"(a) : "l"(p));
    return a;
}

// Interleaved tile layout: tile is 128 rows x 32 k (f16). Physical: 64 rows x 128B.
// element (row, kk): physrow r = row>>1, chunk = ((row&1)*4 + (kk>>3)) ^ (r&7),
// byte = r*128 + chunk*16 + (kk&7)*2.  Conflict-free for cp.async STS and ldmatrix.
__device__ __forceinline__ uint32_t tile_addr(uint32_t base, int row, int kk) {
    int r = row >> 1;
    int c = (((row & 1) << 2) + (kk >> 3)) ^ (r & 7);
    return base + (uint32_t)(r * 128 + c * 16 + (kk & 7) * 2);
}

__device__ __forceinline__ void cp16(uint32_t s, const void* g) {
    asm volatile("cp.async.cg.shared.global [%0], [%1], 16;" :: "r"(s), "l"(g));
}
__device__ __forceinline__ void cp_commit() { asm volatile("cp.async.commit_group;"); }
__device__ __forceinline__ void cp_wait3()  { asm volatile("cp.async.wait_group 3;"); }

__device__ __forceinline__ void ldsm4(uint32_t* d, uint32_t a) {
    asm volatile("ldmatrix.sync.aligned.m8n8.x4.shared.b16 {%0,%1,%2,%3}, [%4];"
        : "=r"(d[0]), "=r"(d[1]), "=r"(d[2]), "=r"(d[3]) : "r"(a));
}
__device__ __forceinline__ void mma_f16(float* d, const uint32_t* a, const uint32_t* b) {
    asm volatile("mma.sync.aligned.m16n8k16.row.col.f32.f16.f16.f32 "
        "{%0,%1,%2,%3}, {%4,%5,%6,%7}, {%8,%9}, {%0,%1,%2,%3};"
        : "+f"(d[0]), "+f"(d[1]), "+f"(d[2]), "+f"(d[3])
        : "r"(a[0]), "r"(a[1]), "r"(a[2]), "r"(a[3]), "r"(b[0]), "r"(b[1]));
}

// ============ fused mma.sync LSTM step (fp16 A, split-fp16 W, 2 passes) ============
// gates[m][n] = (1/WSCALE)*sum_k A[m][k]*Wscaled[n][k] + bias[n]
// A = concat(A0[0:K0], A1[K0:Ktot]); n gate-interleaved: cols 4e..4e+3 = (i,f,g,o) of unit e.
__global__ void __launch_bounds__(256, 2)
lstm_mma_step(const __half* __restrict__ A0, int lda0,
              const __half* __restrict__ A1, int lda1,
              int K0, int Ktot,
              const __half* __restrict__ Wh, const __half* __restrict__ Wl, int ldw,
              const float* __restrict__ bias,
              float* __restrict__ c_inout,
              __half* __restrict__ H,
              float* __restrict__ Hf)
{
    extern __shared__ char smem[];
    const uint32_t sbase = smem_u32(smem);
    const int tid  = threadIdx.x;
    const int lane = tid & 31;
    const int warp = tid >> 5;
    const int wm = warp >> 2;          // 0..1
    const int wn = warp & 3;           // 0..3
    const int n0 = blockIdx.x * 128;
    const int m0 = blockIdx.y * 128;

    const int NC = Ktot >> 5;          // 32-k stages

    // ---- stage issue: 6 cp.async per thread (A x2, Bh x2, Bl x2) ----
    auto issue = [&](int st) {
        const int kstW = st << 5;
        int kstA = kstW;
        const char* pA = (const char*)A0;
        int lda = lda0;
        if (kstA >= K0) { pA = (const char*)A1; lda = lda1; kstA -= K0; }
        const uint32_t sb = sbase + (uint32_t)((st & (NSTAGE - 1)) * STAGE_BYTES);
#pragma unroll
        for (int p = 0; p < 2; p++) {
            const int ch = tid + p * 256;
            const int row = ch >> 2, c = ch & 3;
            // A
            cp16(tile_addr(sb + OFF_A, row, c * 8),
                 pA + ((size_t)(m0 + row) * lda + kstA + c * 8) * 2);
            // B hi / lo
            const uint32_t soB = tile_addr(sb + OFF_BH, row, c * 8);
            const size_t gb = ((size_t)(n0 + row) * ldw + kstW + c * 8) * 2;
            cp16(soB, (const char*)Wh + gb);
            cp16(soB + (OFF_BL - OFF_BH), (const char*)Wl + gb);
        }
        cp_commit();
    };

    issue(0);
    issue(1);
    issue(2);

    float acc[16][4];
#pragma unroll
    for (int i = 0; i < 16; i++)
#pragma unroll
        for (int j = 0; j < 4; j++) acc[i][j] = 0.f;

    // lane-derived ldmatrix row/col offsets
    const int laA_r = lane & 15;            // row within m16
    const int laA_k = (lane >> 4) * 8;      // k half
    const int laB_r = (lane & 7) + ((lane >> 4) & 1) * 8;   // n within 16
    const int laB_k = ((lane >> 3) & 1) * 8;                // k half

    for (int cs = 0; cs < NC; cs++) {
        if (cs + 3 < NC) issue(cs + 3); else cp_commit();
        cp_wait3();
        __syncthreads();

        const uint32_t sb = sbase + (uint32_t)((cs & (NSTAGE - 1)) * STAGE_BYTES);

#pragma unroll
        for (int h = 0; h < 2; h++) {
            const int kk0 = h * 16;
            uint32_t Af[4][4], Bh_[8], Bl_[8];
#pragma unroll
            for (int i = 0; i < 4; i++)
                ldsm4(Af[i], tile_addr(sb + OFF_A, wm * 64 + i * 16 + laA_r, kk0 + laA_k));
            ldsm4(&Bh_[0], tile_addr(sb + OFF_BH, wn * 32 + laB_r,      kk0 + laB_k));
            ldsm4(&Bh_[4], tile_addr(sb + OFF_BH, wn * 32 + 16 + laB_r, kk0 + laB_k));
#pragma unroll
            for (int i = 0; i < 4; i++)
#pragma unroll
                for (int j = 0; j < 4; j++)
                    mma_f16(acc[i * 4 + j], Af[i], &Bh_[j * 2]);
            ldsm4(&Bl_[0], tile_addr(sb + OFF_BL, wn * 32 + laB_r,      kk0 + laB_k));
            ldsm4(&Bl_[4], tile_addr(sb + OFF_BL, wn * 32 + 16 + laB_r, kk0 + laB_k));
#pragma unroll
            for (int i = 0; i < 4; i++)
#pragma unroll
                for (int j = 0; j < 4; j++)
                    mma_f16(acc[i * 4 + j], Af[i], &Bl_[j * 2]);
        }
        __syncthreads();
    }

    // ---- fused LSTM epilogue (register-resident) ----
    // thread lane covers rows (lane>>2)+{0,8}, col pair (lane&3)*2+{0,1} of each 16x8 tile.
    // pair (lane, lane^1) jointly owns a gate quad; shfl_xor(1) assembles it.
    const int pairpos = lane & 1;
    const int rbase = lane >> 2;
    const int elocal = (lane >> 1) & 1;

#pragma unroll
    for (int i = 0; i < 4; i++) {
#pragma unroll
        for (int j = 0; j < 4; j++) {
            float* a = acc[i * 4 + j];
            float r0 = __shfl_xor_sync(0xffffffffu, a[0], 1);
            float r1 = __shfl_xor_sync(0xffffffffu, a[1], 1);
            float r2 = __shfl_xor_sync(0xffffffffu, a[2], 1);
            float r3 = __shfl_xor_sync(0xffffffffu, a[3], 1);
            float gi, gf, gg, go;
            if (pairpos == 0) { gi = a[0]; gf = a[1]; gg = r0; go = r1; }   // row rbase
            else              { gi = r2;  gf = r3;  gg = a[2]; go = a[3]; } // row rbase+8
            const int m = m0 + wm * 64 + i * 16 + rbase + pairpos * 8;
            const int e = ((n0 + wn * 32 + j * 8) >> 2) + elocal;

            const float4 bq = ((const float4*)bias)[e];
            gi = fmaf(gi, WSCALE_INV, bq.x);
            gf = fmaf(gf, WSCALE_INV, bq.y);
            gg = fmaf(gg, WSCALE_INV, bq.z);
            go = fmaf(go, WSCALE_INV, bq.w);

            const size_t off = (size_t)m * EE + e;
            const float co = c_inout[off];
            const float cn = sigmoidf_(gf) * co + sigmoidf_(gi) * tanhf_(gg);
            const float hn = sigmoidf_(go) * tanhf_(cn);
            c_inout[off] = cn;
            H[off] = __float2half_rn(hn);
            if (Hf) Hf[off] = hn;
        }
    }
}

// ============ prep kernels ============
// permuted gate col n -> original row r = (n%4)*512 + n/4  (quad (i,f,g,o) per hidden e)
__global__ void prep_weights(const float* __restrict__ e1Whh,
                             const float* __restrict__ e2Wih, const float* __restrict__ e2Whh,
                             const float* __restrict__ d1Wih, const float* __restrict__ d1Whh,
                             const float* __restrict__ e2bih, const float* __restrict__ e2bhh,
                             const float* __restrict__ d1bih, const float* __restrict__ d1bhh)
{
    int n = blockIdx.y;
    int kk = blockIdx.x * 256 + threadIdx.x;
    if (kk >= K1 + K2 + KD + KD) return;
    int r = (n & 3) * 512 + (n >> 2);
    float v; __half *ph, *pl; long o;
    if (kk < K1) {
        v = (kk < 512) ? e1Whh[(long)r * 512 + kk] : 0.f;   // 512..575 pad; 512..545 overwritten by prep_wc
        ph = g_W1h; pl = g_W1l; o = (long)n * K1 + kk;
    } else if (kk < K1 + K2) {
        int k = kk - K1;
        v = (k < 512) ? e2Wih[(long)r * 512 + k] : e2Whh[(long)r * 512 + (k - 512)];
        ph = g_W2h; pl = g_W2l; o = (long)n * K2 + k;
    } else if (kk < K1 + K2 + KD) {
        int k = kk - (K1 + K2);
        v = d1Whh[(long)r * 512 + k];
        ph = g_WD1h; pl = g_WD1l; o = (long)n * KD + k;
    } else {
        int k = kk - (K1 + K2 + KD);
        v = d1Wih[(long)r * 512 + k] + d1Whh[(long)r * 512 + k];
        ph = g_WDrh; pl = g_WDrl; o = (long)n * KD + k;
    }
    __half hi, lo;
    split_f16(v * WSCALE, hi, lo);
    ph[o] = hi; pl[o] = lo;
    if (kk == 0) {
        g_b2[n] = e2bih[r] + e2bhh[r];
        g_bd[n] = d1bih[r] + d1bhh[r];
    }
}

// Wc = e1Wih @ enc_lin_W folded into W1 rows 512..545; b1 = e1Wih·enc_b + biases
__global__ void prep_wc(const float* __restrict__ e1Wih,
                        const float* __restrict__ encW, const float* __restrict__ encb,
                        const float* __restrict__ e1bih, const float* __restrict__ e1bhh)
{
    int n = blockIdx.x;
    int r = (n & 3) * 512 + (n >> 2);
    __shared__ float wr[512];
    for (int e = threadIdx.x; e < 512; e += blockDim.x) wr[e] = e1Wih[(long)r * 512 + e];
    __syncthreads();
    int t = threadIdx.x;
    if (t < POSE) {
        float acc = 0.f;
        for (int e = 0; e < 512; e++) acc = fmaf(wr[e], encW[e * POSE + t], acc);
        __half hi, lo;
        split_f16(acc * WSCALE, hi, lo);
        g_W1h[(long)n * K1 + 512 + t] = hi;
        g_W1l[(long)n * K1 + 512 + t] = lo;
    } else if (t == POSE) {
        float acc = e1bih[r] + e1bhh[r];
        for (int e = 0; e < 512; e++) acc = fmaf(wr[e], encb[e], acc);
        g_b1[n] = acc;
    }
}

__global__ void prep_x(const float* __restrict__ x) {
    long idx = (long)blockIdx.x * 256 + threadIdx.x;
    if (idx >= (long)TT * BB * 64) return;
    int c = (int)(idx & 63);
    int b = (int)((idx >> 6) & (BB - 1));
    int t = (int)(idx >> 17);
    float v = (c < POSE) ? x[(long)b * (TT * POSE) + t * POSE + c] : 0.f;
    g_x[idx] = __float2half_rn(v);
}

__global__ void zero_init() {
    long i = (long)blockIdx.x * 256 + threadIdx.x;
    if (i < (long)BE) {
        __half z = __float2half_rn(0.f);
        g_h1[0][i] = z;
        g_h2[0][i] = z;
        g_c1[i] = 0.f; g_c2[i] = 0.f;
    }
}

__global__ void final_linear(const float* __restrict__ preds,
                             const float* __restrict__ W, const float* __restrict__ bias,
                             float* __restrict__ out)
{
    int bf = blockIdx.x;
    int f = bf % FUT;
    int b = bf / FUT;
    __shared__ float row[512];
    const float* src = preds + ((size_t)f * BB + b) * EE;
    for (int i = threadIdx.x; i < 512; i += blockDim.x) row[i] = src[i];
    __syncthreads();
    int p = threadIdx.x;
    if (p < POSE) {
        const float* w = W + (size_t)p * 512;
        float acc = bias[p];
        for (int e = 0; e < 512; e++) acc = fmaf(row[e], w[e], acc);
        out[(size_t)b * (FUT * POSE) + f * POSE + p] = acc;
    }
}

// ============ launch ============
extern "C" void kernel_launch(void* const* d_in, const int* in_sizes, int n_in,
                              void* d_out, int out_size)
{
    (void)in_sizes; (void)n_in; (void)out_size;
    const float* x     = (const float*)d_in[0];
    const float* encW  = (const float*)d_in[1];
    const float* encb  = (const float*)d_in[2];
    const float* e1Wih = (const float*)d_in[3];
    const float* e1Whh = (const float*)d_in[4];
    const float* e1bih = (const float*)d_in[5];
    const float* e1bhh = (const float*)d_in[6];
    const float* e2Wih = (const float*)d_in[7];
    const float* e2Whh = (const float*)d_in[8];
    const float* e2bih = (const float*)d_in[9];
    const float* e2bhh = (const float*)d_in[10];
    const float* d1Wih = (const float*)d_in[11];
    const float* d1Whh = (const float*)d_in[12];
    const float* d1bih = (const float*)d_in[13];
    const float* d1bhh = (const float*)d_in[14];
    const float* dW    = (const float*)d_in[15];
    const float* db    = (const float*)d_in[16];
    float* out = (float*)d_out;

    __half *h1, *h2, *dh, *W1h, *W1l, *W2h, *W2l, *WD1h, *WD1l, *WDrh, *WDrl, *xh;
    float *c1, *c2, *b1, *b2, *bd, *preds;
    cudaGetSymbolAddress((void**)&h1,  g_h1);
    cudaGetSymbolAddress((void**)&h2,  g_h2);
    cudaGetSymbolAddress((void**)&dh,  g_dh);
    cudaGetSymbolAddress((void**)&c1,  g_c1);   cudaGetSymbolAddress((void**)&c2,  g_c2);
    cudaGetSymbolAddress((void**)&W1h, g_W1h);  cudaGetSymbolAddress((void**)&W1l, g_W1l);
    cudaGetSymbolAddress((void**)&W2h, g_W2h);  cudaGetSymbolAddress((void**)&W2l, g_W2l);
    cudaGetSymbolAddress((void**)&WD1h, g_WD1h); cudaGetSymbolAddress((void**)&WD1l, g_WD1l);
    cudaGetSymbolAddress((void**)&WDrh, g_WDrh); cudaGetSymbolAddress((void**)&WDrl, g_WDrl);
    cudaGetSymbolAddress((void**)&xh,  g_x);
    cudaGetSymbolAddress((void**)&b1,  g_b1);   cudaGetSymbolAddress((void**)&b2,  g_b2);
    cudaGetSymbolAddress((void**)&bd,  g_bd);   cudaGetSymbolAddress((void**)&preds, g_preds);

    cudaFuncSetAttribute(lstm_mma_step, cudaFuncAttributeMaxDynamicSharedMemorySize, SMEM_TOTAL);

    prep_weights<<<dim3((K1 + K2 + 2 * KD + 255) / 256, 2048), 256>>>(
        e1Whh, e2Wih, e2Whh, d1Wih, d1Whh, e2bih, e2bhh, d1bih, d1bhh);
    prep_wc<<<2048, 64>>>(e1Wih, encW, encb, e1bih, e1bhh);
    prep_x<<<(int)(((long)TT * BB * 64 + 255) / 256), 256>>>(x);
    zero_init<<<(BE + 255) / 256, 256>>>();

    dim3 grid(16, 16);
    for (int t = 0; t < TT; t++) {
        int in = t & 1, ot = (t + 1) & 1;
        // cell 1: A = [h1 | x_t slab], K = 576
        lstm_mma_step<<<grid, 256, SMEM_TOTAL>>>(
            h1 + (size_t)in * BE, EE,
            xh + (size_t)t * BB * 64, 64,
            512, K1, W1h, W1l, K1, b1, c1,
            h1 + (size_t)ot * BE, nullptr);
        // cell 2: A = [h1_new | h2], K = 1024
        lstm_mma_step<<<grid, 256, SMEM_TOTAL>>>(
            h1 + (size_t)ot * BE, EE,
            h2 + (size_t)in * BE, EE,
            512, K2, W2h, W2l, K2, b2, c2,
            h2 + (size_t)ot * BE, nullptr);
    }
    // encoder final h2/c2 in slot 0 (t=99 -> ot=0)

    // decoder step 0: input zeros -> gates = h2 @ Whh^T + bd
    lstm_mma_step<<<grid, 256, SMEM_TOTAL>>>(
        h2, EE, nullptr, 0,
        KD, KD, WD1h, WD1l, KD, bd, c2,
        dh, preds);
    // steps 1..9: out == h -> gates = h @ (Wih+Whh)^T + bd
    for (int f = 1; f < FUT; f++) {
        int ip = (f - 1) & 1, op = f & 1;
        lstm_mma_step<<<grid, 256, SMEM_TOTAL>>>(
            dh + (size_t)ip * BE, EE, nullptr, 0,
            KD, KD, WDrh, WDrl, KD, bd, c2,
            dh + (size_t)op * BE, preds + (size_t)f * BE);
    }

    final_linear<<<BB * FUT, 64>>>(preds, dW, db, out);
}

// round 7
// speedup vs baseline: 2.3952x; 1.1867x over previous
#include <cuda_runtime.h>
#include <cuda_fp16.h>
#include <stdint.h>
#include <stddef.h>

#define BB 2048
#define TT 100
#define EE 512
#define POSE 34
#define FUT 10
#define BE (BB*EE)

#define K1 576        // cell1: 512 (h1) + 64 (x slab: 34 real + pad)
#define K2 1024       // cell2: 512 (h1_new) + 512 (h2)
#define KD 512        // decoder

// SMEM pipeline: 4 stages x 16KB (A 8K | B 8K)
#define STAGE_BYTES 16384
#define OFF_A 0
#define OFF_B 8192
#define NSTAGE 4
#define SMEM_TOTAL (NSTAGE*STAGE_BYTES)

// ---------------- device globals (no allocation allowed) ----------------
__device__ __align__(16) __half g_h1[2][BE];
__device__ __align__(16) __half g_h2[2][BE];
__device__ __align__(16) __half g_dh[2][BE];
__device__ __align__(16) float g_c1[BE], g_c2[BE];
__device__ __align__(16) __half g_W1[2048*K1];
__device__ __align__(16) __half g_W2[2048*K2];
__device__ __align__(16) __half g_WD1[2048*KD];
__device__ __align__(16) __half g_WDr[2048*KD];
__device__ __align__(16) __half g_x[(size_t)TT*BB*64];
__device__ __align__(16) float g_b1[2048], g_b2[2048], g_bd[2048];
__device__ __align__(16) float g_preds[(size_t)FUT*BE];

// ---------------- helpers ----------------
__device__ __forceinline__ float sigmoidf_(float x) { return __fdividef(1.f, 1.f + __expf(-x)); }
__device__ __forceinline__ float tanhf_(float x)    { return 1.f - __fdividef(2.f, __expf(2.f*x) + 1.f); }

__device__ __forceinline__ uint32_t smem_u32(const void* p) {
    uint32_t a;
    asm("{ .reg .u64 t; cvta.to.shared.u64 t, %1; cvt.u32.u64 %0, t; }" : "=r"(a) : "l"(p));
    return a;
}

// Interleaved tile layout: tile is 128 rows x 32 k (f16). Physical: 64 rows x 128B.
// element (row, kk): physrow r = row>>1, chunk = ((row&1)*4 + (kk>>3)) ^ (r&7),
// byte = r*128 + chunk*16 + (kk&7)*2.  Conflict-free for cp.async STS and ldmatrix.
__device__ __forceinline__ uint32_t tile_addr(uint32_t base, int row, int kk) {
    int r = row >> 1;
    int c = (((row & 1) << 2) + (kk >> 3)) ^ (r & 7);
    return base + (uint32_t)(r * 128 + c * 16 + (kk & 7) * 2);
}

__device__ __forceinline__ void cp16(uint32_t s, const void* g) {
    asm volatile("cp.async.cg.shared.global [%0], [%1], 16;" :: "r"(s), "l"(g));
}
__device__ __forceinline__ void cp_commit() { asm volatile("cp.async.commit_group;"); }
__device__ __forceinline__ void cp_wait3()  { asm volatile("cp.async.wait_group 3;"); }

__device__ __forceinline__ void ldsm4(uint32_t* d, uint32_t a) {
    asm volatile("ldmatrix.sync.aligned.m8n8.x4.shared.b16 {%0,%1,%2,%3}, [%4];"
        : "=r"(d[0]), "=r"(d[1]), "=r"(d[2]), "=r"(d[3]) : "r"(a));
}
__device__ __forceinline__ void mma_f16(float* d, const uint32_t* a, const uint32_t* b) {
    asm volatile("mma.sync.aligned.m16n8k16.row.col.f32.f16.f16.f32 "
        "{%0,%1,%2,%3}, {%4,%5,%6,%7}, {%8,%9}, {%0,%1,%2,%3};"
        : "+f"(d[0]), "+f"(d[1]), "+f"(d[2]), "+f"(d[3])
        : "r"(a[0]), "r"(a[1]), "r"(a[2]), "r"(a[3]), "r"(b[0]), "r"(b[1]));
}

// ============ fused mma.sync LSTM step (fp16 A, fp16 W, single pass) ============
// gates[m][n] = sum_k A[m][k]*W[n][k] + bias[n]
// A = concat(A0[0:K0], A1[K0:Ktot]); n gate-interleaved: cols 4e..4e+3 = (i,f,g,o) of unit e.
__global__ void __launch_bounds__(256, 2)
lstm_mma_step(const __half* __restrict__ A0, int lda0,
              const __half* __restrict__ A1, int lda1,
              int K0, int Ktot,
              const __half* __restrict__ W, int ldw,
              const float* __restrict__ bias,
              float* __restrict__ c_inout,
              __half* __restrict__ H,
              float* __restrict__ Hf)
{
    extern __shared__ char smem[];
    const uint32_t sbase = smem_u32(smem);
    const int tid  = threadIdx.x;
    const int lane = tid & 31;
    const int warp = tid >> 5;
    const int wm = warp >> 2;          // 0..1
    const int wn = warp & 3;           // 0..3
    const int n0 = blockIdx.x * 128;
    const int m0 = blockIdx.y * 128;

    const int NC = Ktot >> 5;          // 32-k stages

    // ---- stage issue: 4 cp.async per thread (A x2, B x2) ----
    auto issue = [&](int st) {
        const int kstW = st << 5;
        int kstA = kstW;
        const char* pA = (const char*)A0;
        int lda = lda0;
        if (kstA >= K0) { pA = (const char*)A1; lda = lda1; kstA -= K0; }
        const uint32_t sb = sbase + (uint32_t)((st & (NSTAGE - 1)) * STAGE_BYTES);
#pragma unroll
        for (int p = 0; p < 2; p++) {
            const int ch = tid + p * 256;
            const int row = ch >> 2, c = ch & 3;
            cp16(tile_addr(sb + OFF_A, row, c * 8),
                 pA + ((size_t)(m0 + row) * lda + kstA + c * 8) * 2);
            cp16(tile_addr(sb + OFF_B, row, c * 8),
                 (const char*)W + ((size_t)(n0 + row) * ldw + kstW + c * 8) * 2);
        }
        cp_commit();
    };

    issue(0);
    issue(1);
    issue(2);

    float acc[16][4];
#pragma unroll
    for (int i = 0; i < 16; i++)
#pragma unroll
        for (int j = 0; j < 4; j++) acc[i][j] = 0.f;

    // lane-derived ldmatrix row/col offsets
    const int laA_r = lane & 15;            // row within m16
    const int laA_k = (lane >> 4) * 8;      // k half
    const int laB_r = (lane & 7) + ((lane >> 4) & 1) * 8;   // n within 16
    const int laB_k = ((lane >> 3) & 1) * 8;                // k half

    for (int cs = 0; cs < NC; cs++) {
        if (cs + 3 < NC) issue(cs + 3); else cp_commit();
        cp_wait3();
        __syncthreads();

        const uint32_t sb = sbase + (uint32_t)((cs & (NSTAGE - 1)) * STAGE_BYTES);

#pragma unroll
        for (int h = 0; h < 2; h++) {
            const int kk0 = h * 16;
            uint32_t Af[4][4], Bf[8];
#pragma unroll
            for (int i = 0; i < 4; i++)
                ldsm4(Af[i], tile_addr(sb + OFF_A, wm * 64 + i * 16 + laA_r, kk0 + laA_k));
            ldsm4(&Bf[0], tile_addr(sb + OFF_B, wn * 32 + laB_r,      kk0 + laB_k));
            ldsm4(&Bf[4], tile_addr(sb + OFF_B, wn * 32 + 16 + laB_r, kk0 + laB_k));
#pragma unroll
            for (int i = 0; i < 4; i++)
#pragma unroll
                for (int j = 0; j < 4; j++)
                    mma_f16(acc[i * 4 + j], Af[i], &Bf[j * 2]);
        }
        __syncthreads();
    }

    // ---- fused LSTM epilogue (register-resident) ----
    // thread lane covers rows (lane>>2)+{0,8}, col pair (lane&3)*2+{0,1} of each 16x8 tile.
    // pair (lane, lane^1) jointly owns a gate quad; shfl_xor(1) assembles it.
    const int pairpos = lane & 1;
    const int rbase = lane >> 2;
    const int elocal = (lane >> 1) & 1;

#pragma unroll
    for (int i = 0; i < 4; i++) {
#pragma unroll
        for (int j = 0; j < 4; j++) {
            float* a = acc[i * 4 + j];
            float r0 = __shfl_xor_sync(0xffffffffu, a[0], 1);
            float r1 = __shfl_xor_sync(0xffffffffu, a[1], 1);
            float r2 = __shfl_xor_sync(0xffffffffu, a[2], 1);
            float r3 = __shfl_xor_sync(0xffffffffu, a[3], 1);
            float gi, gf, gg, go;
            if (pairpos == 0) { gi = a[0]; gf = a[1]; gg = r0; go = r1; }   // row rbase
            else              { gi = r2;  gf = r3;  gg = a[2]; go = a[3]; } // row rbase+8
            const int m = m0 + wm * 64 + i * 16 + rbase + pairpos * 8;
            const int e = ((n0 + wn * 32 + j * 8) >> 2) + elocal;

            const float4 bq = ((const float4*)bias)[e];
            gi += bq.x; gf += bq.y; gg += bq.z; go += bq.w;

            const size_t off = (size_t)m * EE + e;
            const float co = c_inout[off];
            const float cn = sigmoidf_(gf) * co + sigmoidf_(gi) * tanhf_(gg);
            const float hn = sigmoidf_(go) * tanhf_(cn);
            c_inout[off] = cn;
            H[off] = __float2half_rn(hn);
            if (Hf) Hf[off] = hn;
        }
    }
}

// ============ prep kernels ============
// permuted gate col n -> original row r = (n%4)*512 + n/4  (quad (i,f,g,o) per hidden e)
__global__ void prep_weights(const float* __restrict__ e1Whh,
                             const float* __restrict__ e2Wih, const float* __restrict__ e2Whh,
                             const float* __restrict__ d1Wih, const float* __restrict__ d1Whh,
                             const float* __restrict__ e2bih, const float* __restrict__ e2bhh,
                             const float* __restrict__ d1bih, const float* __restrict__ d1bhh)
{
    int n = blockIdx.y;
    int kk = blockIdx.x * 256 + threadIdx.x;
    if (kk >= K1 + K2 + KD + KD) return;
    int r = (n & 3) * 512 + (n >> 2);
    float v; __half* ph; long o;
    if (kk < K1) {
        v = (kk < 512) ? e1Whh[(long)r * 512 + kk] : 0.f;   // 512..575 pad; 512..545 overwritten by prep_wc
        ph = g_W1; o = (long)n * K1 + kk;
    } else if (kk < K1 + K2) {
        int k = kk - K1;
        v = (k < 512) ? e2Wih[(long)r * 512 + k] : e2Whh[(long)r * 512 + (k - 512)];
        ph = g_W2; o = (long)n * K2 + k;
    } else if (kk < K1 + K2 + KD) {
        int k = kk - (K1 + K2);
        v = d1Whh[(long)r * 512 + k];
        ph = g_WD1; o = (long)n * KD + k;
    } else {
        int k = kk - (K1 + K2 + KD);
        v = d1Wih[(long)r * 512 + k] + d1Whh[(long)r * 512 + k];
        ph = g_WDr; o = (long)n * KD + k;
    }
    ph[o] = __float2half_rn(v);
    if (kk == 0) {
        g_b2[n] = e2bih[r] + e2bhh[r];
        g_bd[n] = d1bih[r] + d1bhh[r];
    }
}

// Wc = e1Wih @ enc_lin_W folded into W1 rows 512..545; b1 = e1Wih·enc_b + biases
__global__ void prep_wc(const float* __restrict__ e1Wih,
                        const float* __restrict__ encW, const float* __restrict__ encb,
                        const float* __restrict__ e1bih, const float* __restrict__ e1bhh)
{
    int n = blockIdx.x;
    int r = (n & 3) * 512 + (n >> 2);
    __shared__ float wr[512];
    for (int e = threadIdx.x; e < 512; e += blockDim.x) wr[e] = e1Wih[(long)r * 512 + e];
    __syncthreads();
    int t = threadIdx.x;
    if (t < POSE) {
        float acc = 0.f;
        for (int e = 0; e < 512; e++) acc = fmaf(wr[e], encW[e * POSE + t], acc);
        g_W1[(long)n * K1 + 512 + t] = __float2half_rn(acc);
    } else if (t == POSE) {
        float acc = e1bih[r] + e1bhh[r];
        for (int e = 0; e < 512; e++) acc = fmaf(wr[e], encb[e], acc);
        g_b1[n] = acc;
    }
}

__global__ void prep_x(const float* __restrict__ x) {
    long idx = (long)blockIdx.x * 256 + threadIdx.x;
    if (idx >= (long)TT * BB * 64) return;
    int c = (int)(idx & 63);
    int b = (int)((idx >> 6) & (BB - 1));
    int t = (int)(idx >> 17);
    float v = (c < POSE) ? x[(long)b * (TT * POSE) + t * POSE + c] : 0.f;
    g_x[idx] = __float2half_rn(v);
}

__global__ void zero_init() {
    long i = (long)blockIdx.x * 256 + threadIdx.x;
    if (i < (long)BE) {
        __half z = __float2half_rn(0.f);
        g_h1[0][i] = z;
        g_h2[0][i] = z;
        g_c1[i] = 0.f; g_c2[i] = 0.f;
    }
}

__global__ void final_linear(const float* __restrict__ preds,
                             const float* __restrict__ W, const float* __restrict__ bias,
                             float* __restrict__ out)
{
    int bf = blockIdx.x;
    int f = bf % FUT;
    int b = bf / FUT;
    __shared__ float row[512];
    const float* src = preds + ((size_t)f * BB + b) * EE;
    for (int i = threadIdx.x; i < 512; i += blockDim.x) row[i] = src[i];
    __syncthreads();
    int p = threadIdx.x;
    if (p < POSE) {
        const float* w = W + (size_t)p * 512;
        float acc = bias[p];
        for (int e = 0; e < 512; e++) acc = fmaf(row[e], w[e], acc);
        out[(size_t)b * (FUT * POSE) + f * POSE + p] = acc;
    }
}

// ============ launch ============
extern "C" void kernel_launch(void* const* d_in, const int* in_sizes, int n_in,
                              void* d_out, int out_size)
{
    (void)in_sizes; (void)n_in; (void)out_size;
    const float* x     = (const float*)d_in[0];
    const float* encW  = (const float*)d_in[1];
    const float* encb  = (const float*)d_in[2];
    const float* e1Wih = (const float*)d_in[3];
    const float* e1Whh = (const float*)d_in[4];
    const float* e1bih = (const float*)d_in[5];
    const float* e1bhh = (const float*)d_in[6];
    const float* e2Wih = (const float*)d_in[7];
    const float* e2Whh = (const float*)d_in[8];
    const float* e2bih = (const float*)d_in[9];
    const float* e2bhh = (const float*)d_in[10];
    const float* d1Wih = (const float*)d_in[11];
    const float* d1Whh = (const float*)d_in[12];
    const float* d1bih = (const float*)d_in[13];
    const float* d1bhh = (const float*)d_in[14];
    const float* dW    = (const float*)d_in[15];
    const float* db    = (const float*)d_in[16];
    float* out = (float*)d_out;

    __half *h1, *h2, *dh, *W1, *W2, *WD1, *WDr, *xh;
    float *c1, *c2, *b1, *b2, *bd, *preds;
    cudaGetSymbolAddress((void**)&h1,  g_h1);
    cudaGetSymbolAddress((void**)&h2,  g_h2);
    cudaGetSymbolAddress((void**)&dh,  g_dh);
    cudaGetSymbolAddress((void**)&c1,  g_c1);   cudaGetSymbolAddress((void**)&c2,  g_c2);
    cudaGetSymbolAddress((void**)&W1,  g_W1);   cudaGetSymbolAddress((void**)&W2,  g_W2);
    cudaGetSymbolAddress((void**)&WD1, g_WD1);  cudaGetSymbolAddress((void**)&WDr, g_WDr);
    cudaGetSymbolAddress((void**)&xh,  g_x);
    cudaGetSymbolAddress((void**)&b1,  g_b1);   cudaGetSymbolAddress((void**)&b2,  g_b2);
    cudaGetSymbolAddress((void**)&bd,  g_bd);   cudaGetSymbolAddress((void**)&preds, g_preds);

    cudaFuncSetAttribute(lstm_mma_step, cudaFuncAttributeMaxDynamicSharedMemorySize, SMEM_TOTAL);

    prep_weights<<<dim3((K1 + K2 + 2 * KD + 255) / 256, 2048), 256>>>(
        e1Whh, e2Wih, e2Whh, d1Wih, d1Whh, e2bih, e2bhh, d1bih, d1bhh);
    prep_wc<<<2048, 64>>>(e1Wih, encW, encb, e1bih, e1bhh);
    prep_x<<<(int)(((long)TT * BB * 64 + 255) / 256), 256>>>(x);
    zero_init<<<(BE + 255) / 256, 256>>>();

    dim3 grid(16, 16);
    for (int t = 0; t < TT; t++) {
        int in = t & 1, ot = (t + 1) & 1;
        // cell 1: A = [h1 | x_t slab], K = 576
        lstm_mma_step<<<grid, 256, SMEM_TOTAL>>>(
            h1 + (size_t)in * BE, EE,
            xh + (size_t)t * BB * 64, 64,
            512, K1, W1, K1, b1, c1,
            h1 + (size_t)ot * BE, nullptr);
        // cell 2: A = [h1_new | h2], K = 1024
        lstm_mma_step<<<grid, 256, SMEM_TOTAL>>>(
            h1 + (size_t)ot * BE, EE,
            h2 + (size_t)in * BE, EE,
            512, K2, W2, K2, b2, c2,
            h2 + (size_t)ot * BE, nullptr);
    }
    // encoder final h2/c2 in slot 0 (t=99 -> ot=0)

    // decoder step 0: input zeros -> gates = h2 @ Whh^T + bd
    lstm_mma_step<<<grid, 256, SMEM_TOTAL>>>(
        h2, EE, nullptr, 0,
        KD, KD, WD1, KD, bd, c2,
        dh, preds);
    // steps 1..9: out == h -> gates = h @ (Wih+Whh)^T + bd
    for (int f = 1; f < FUT; f++) {
        int ip = (f - 1) & 1, op = f & 1;
        lstm_mma_step<<<grid, 256, SMEM_TOTAL>>>(
            dh + (size_t)ip * BE, EE, nullptr, 0,
            KD, KD, WDr, KD, bd, c2,
            dh + (size_t)op * BE, preds + (size_t)f * BE);
    }

    final_linear<<<BB * FUT, 64>>>(preds, dW, db, out);
}

// round 8
// speedup vs baseline: 2.5392x; 1.0601x over previous
#include <cuda_runtime.h>
#include <cuda_fp16.h>
#include <stdint.h>
#include <stddef.h>

#define BB 2048
#define TT 100
#define EE 512
#define POSE 34
#define FUT 10
#define BE (BB*EE)

#define K1 576        // cell1: 512 (h1) + 64 (x slab: 34 real + pad)
#define K2 1024       // cell2: 512 (h1_new) + 512 (h2)
#define KD 512        // decoder

// SMEM pipeline: 5 stages x 16KB (A 8K | B 8K); single sync per chunk (WAR-safe at 5 stages)
#define STAGE_BYTES 16384
#define OFF_A 0
#define OFF_B 8192
#define NSTAGE 5
#define SMEM_TOTAL (NSTAGE*STAGE_BYTES)

// ---------------- device globals (no allocation allowed) ----------------
__device__ __align__(16) __half g_h1[2][BE];
__device__ __align__(16) __half g_h2[2][BE];
__device__ __align__(16) __half g_dh[2][BE];
__device__ __align__(16) float g_c1[BE], g_c2[BE];
__device__ __align__(16) __half g_W1[2048*K1];
__device__ __align__(16) __half g_W2[2048*K2];
__device__ __align__(16) __half g_WD1[2048*KD];
__device__ __align__(16) __half g_WDr[2048*KD];
__device__ __align__(16) __half g_x[(size_t)TT*BB*64];
__device__ __align__(16) float g_b1[2048], g_b2[2048], g_bd[2048];
__device__ __align__(16) float g_preds[(size_t)FUT*BE];

// ---------------- helpers ----------------
__device__ __forceinline__ float sigmoidf_(float x) { return __fdividef(1.f, 1.f + __expf(-x)); }
__device__ __forceinline__ float tanhf_(float x)    { return 1.f - __fdividef(2.f, __expf(2.f*x) + 1.f); }

__device__ __forceinline__ uint32_t smem_u32(const void* p) {
    uint32_t a;
    asm("{ .reg .u64 t; cvta.to.shared.u64 t, %1; cvt.u32.u64 %0, t; }" : "=r"(a) : "l"(p));
    return a;
}

// Interleaved tile layout: tile is 128 rows x 32 k (f16). Physical: 64 rows x 128B.
// element (row, kk): physrow r = row>>1, chunk = ((row&1)*4 + (kk>>3)) ^ (r&7),
// byte = r*128 + chunk*16 + (kk&7)*2.  Conflict-free for cp.async STS and ldmatrix.
__device__ __forceinline__ uint32_t tile_addr(uint32_t base, int row, int kk) {
    int r = row >> 1;
    int c = (((row & 1) << 2) + (kk >> 3)) ^ (r & 7);
    return base + (uint32_t)(r * 128 + c * 16 + (kk & 7) * 2);
}

__device__ __forceinline__ void cp16(uint32_t s, const void* g) {
    asm volatile("cp.async.cg.shared.global [%0], [%1], 16;" :: "r"(s), "l"(g));
}
__device__ __forceinline__ void cp_commit() { asm volatile("cp.async.commit_group;"); }
__device__ __forceinline__ void cp_wait3()  { asm volatile("cp.async.wait_group 3;"); }

__device__ __forceinline__ void ldsm4(uint32_t* d, uint32_t a) {
    asm volatile("ldmatrix.sync.aligned.m8n8.x4.shared.b16 {%0,%1,%2,%3}, [%4];"
        : "=r"(d[0]), "=r"(d[1]), "=r"(d[2]), "=r"(d[3]) : "r"(a));
}
__device__ __forceinline__ void mma_f16(float* d, const uint32_t* a, const uint32_t* b) {
    asm volatile("mma.sync.aligned.m16n8k16.row.col.f32.f16.f16.f32 "
        "{%0,%1,%2,%3}, {%4,%5,%6,%7}, {%8,%9}, {%0,%1,%2,%3};"
        : "+f"(d[0]), "+f"(d[1]), "+f"(d[2]), "+f"(d[3])
        : "r"(a[0]), "r"(a[1]), "r"(a[2]), "r"(a[3]), "r"(b[0]), "r"(b[1]));
}

// ============ fused mma.sync LSTM step (fp16, warp tile 64x64, 4 warps) ============
// gates[m][n] = sum_k A[m][k]*W[n][k] + bias[n]
// A = concat(A0[0:K0], A1[K0:Ktot]); n gate-interleaved: cols 4e..4e+3 = (i,f,g,o) of unit e.
__global__ void __launch_bounds__(128, 2)
lstm_mma_step(const __half* __restrict__ A0, int lda0,
              const __half* __restrict__ A1, int lda1,
              int K0, int Ktot,
              const __half* __restrict__ W, int ldw,
              const float* __restrict__ bias,
              float* __restrict__ c_inout,
              __half* __restrict__ H,
              float* __restrict__ Hf)
{
    extern __shared__ char smem[];
    const uint32_t sbase = smem_u32(smem);
    const int tid  = threadIdx.x;
    const int lane = tid & 31;
    const int warp = tid >> 5;         // 0..3
    const int wm = warp >> 1;          // 0..1  (m 64-half)
    const int wn = warp & 1;           // 0..1  (n 64-half)
    const int n0 = blockIdx.x * 128;
    const int m0 = blockIdx.y * 128;

    const int NC = Ktot >> 5;          // 32-k chunks

    // ---- stage issue: 8 cp.async per thread (A x4, B x4) ----
    auto issue = [&](int st) {
        const int kstW = st << 5;
        int kstA = kstW;
        const char* pA = (const char*)A0;
        int lda = lda0;
        if (kstA >= K0) { pA = (const char*)A1; lda = lda1; kstA -= K0; }
        const uint32_t sb = sbase + (uint32_t)((st % NSTAGE) * STAGE_BYTES);
#pragma unroll
        for (int p = 0; p < 4; p++) {
            const int ch = tid + p * 128;
            const int row = ch >> 2, c = ch & 3;
            cp16(tile_addr(sb + OFF_A, row, c * 8),
                 pA + ((size_t)(m0 + row) * lda + kstA + c * 8) * 2);
            cp16(tile_addr(sb + OFF_B, row, c * 8),
                 (const char*)W + ((size_t)(n0 + row) * ldw + kstW + c * 8) * 2);
        }
        cp_commit();
    };

    issue(0);
    issue(1);
    issue(2);

    float acc[32][4];                   // [i*8+jj][..]  i: m16 idx 0..3, jj: n8 idx 0..7
#pragma unroll
    for (int i = 0; i < 32; i++)
#pragma unroll
        for (int j = 0; j < 4; j++) acc[i][j] = 0.f;

    // lane-derived ldmatrix row/col offsets
    const int laA_r = lane & 15;            // row within m16
    const int laA_k = (lane >> 4) * 8;      // k half
    const int laB_r = (lane & 7) + ((lane >> 4) & 1) * 8;   // n within 16
    const int laB_k = ((lane >> 3) & 1) * 8;                // k half

    for (int cs = 0; cs < NC; cs++) {
        if (cs + 3 < NC) issue(cs + 3); else cp_commit();
        cp_wait3();
        __syncthreads();

        const uint32_t sb = sbase + (uint32_t)((cs % NSTAGE) * STAGE_BYTES);

#pragma unroll
        for (int h = 0; h < 2; h++) {
            const int kk0 = h * 16;
            uint32_t Af[4][4], Bf[16];
#pragma unroll
            for (int i = 0; i < 4; i++)
                ldsm4(Af[i], tile_addr(sb + OFF_A, wm * 64 + i * 16 + laA_r, kk0 + laA_k));
#pragma unroll
            for (int j = 0; j < 4; j++)
                ldsm4(&Bf[j * 4], tile_addr(sb + OFF_B, wn * 64 + j * 16 + laB_r, kk0 + laB_k));
#pragma unroll
            for (int i = 0; i < 4; i++)
#pragma unroll
                for (int jj = 0; jj < 8; jj++)
                    mma_f16(acc[i * 8 + jj], Af[i], &Bf[jj * 2]);
        }
    }
    __syncthreads();   // protect last-read stages before exit (cheap, once)

    // ---- fused LSTM epilogue (register-resident) ----
    // per 16x8 mma tile: lane covers rows (lane>>2)+{0,8}, col pair (lane&3)*2+{0,1}.
    // pair (lane, lane^1) jointly owns a gate quad; shfl_xor(1) assembles it.
    const int pairpos = lane & 1;
    const int rbase = lane >> 2;
    const int elocal = (lane >> 1) & 1;

#pragma unroll
    for (int i = 0; i < 4; i++) {
#pragma unroll
        for (int jj = 0; jj < 8; jj++) {
            float* a = acc[i * 8 + jj];
            float r0 = __shfl_xor_sync(0xffffffffu, a[0], 1);
            float r1 = __shfl_xor_sync(0xffffffffu, a[1], 1);
            float r2 = __shfl_xor_sync(0xffffffffu, a[2], 1);
            float r3 = __shfl_xor_sync(0xffffffffu, a[3], 1);
            float gi, gf, gg, go;
            if (pairpos == 0) { gi = a[0]; gf = a[1]; gg = r0; go = r1; }   // row rbase
            else              { gi = r2;  gf = r3;  gg = a[2]; go = a[3]; } // row rbase+8
            const int m = m0 + wm * 64 + i * 16 + rbase + pairpos * 8;
            const int e = ((n0 + wn * 64 + jj * 8) >> 2) + elocal;

            const float4 bq = ((const float4*)bias)[e];
            gi += bq.x; gf += bq.y; gg += bq.z; go += bq.w;

            const size_t off = (size_t)m * EE + e;
            const float co = c_inout[off];
            const float cn = sigmoidf_(gf) * co + sigmoidf_(gi) * tanhf_(gg);
            const float hn = sigmoidf_(go) * tanhf_(cn);
            c_inout[off] = cn;
            H[off] = __float2half_rn(hn);
            if (Hf) Hf[off] = hn;
        }
    }
}

// ============ prep kernels ============
// permuted gate col n -> original row r = (n%4)*512 + n/4  (quad (i,f,g,o) per hidden e)
__global__ void prep_weights(const float* __restrict__ e1Whh,
                             const float* __restrict__ e2Wih, const float* __restrict__ e2Whh,
                             const float* __restrict__ d1Wih, const float* __restrict__ d1Whh,
                             const float* __restrict__ e2bih, const float* __restrict__ e2bhh,
                             const float* __restrict__ d1bih, const float* __restrict__ d1bhh)
{
    int n = blockIdx.y;
    int kk = blockIdx.x * 256 + threadIdx.x;
    if (kk >= K1 + K2 + KD + KD) return;
    int r = (n & 3) * 512 + (n >> 2);
    float v; __half* ph; long o;
    if (kk < K1) {
        v = (kk < 512) ? e1Whh[(long)r * 512 + kk] : 0.f;   // 512..575 pad; 512..545 overwritten by prep_wc
        ph = g_W1; o = (long)n * K1 + kk;
    } else if (kk < K1 + K2) {
        int k = kk - K1;
        v = (k < 512) ? e2Wih[(long)r * 512 + k] : e2Whh[(long)r * 512 + (k - 512)];
        ph = g_W2; o = (long)n * K2 + k;
    } else if (kk < K1 + K2 + KD) {
        int k = kk - (K1 + K2);
        v = d1Whh[(long)r * 512 + k];
        ph = g_WD1; o = (long)n * KD + k;
    } else {
        int k = kk - (K1 + K2 + KD);
        v = d1Wih[(long)r * 512 + k] + d1Whh[(long)r * 512 + k];
        ph = g_WDr; o = (long)n * KD + k;
    }
    ph[o] = __float2half_rn(v);
    if (kk == 0) {
        g_b2[n] = e2bih[r] + e2bhh[r];
        g_bd[n] = d1bih[r] + d1bhh[r];
    }
}

// Wc = e1Wih @ enc_lin_W folded into W1 rows 512..545; b1 = e1Wih·enc_b + biases
__global__ void prep_wc(const float* __restrict__ e1Wih,
                        const float* __restrict__ encW, const float* __restrict__ encb,
                        const float* __restrict__ e1bih, const float* __restrict__ e1bhh)
{
    int n = blockIdx.x;
    int r = (n & 3) * 512 + (n >> 2);
    __shared__ float wr[512];
    for (int e = threadIdx.x; e < 512; e += blockDim.x) wr[e] = e1Wih[(long)r * 512 + e];
    __syncthreads();
    int t = threadIdx.x;
    if (t < POSE) {
        float acc = 0.f;
        for (int e = 0; e < 512; e++) acc = fmaf(wr[e], encW[e * POSE + t], acc);
        g_W1[(long)n * K1 + 512 + t] = __float2half_rn(acc);
    } else if (t == POSE) {
        float acc = e1bih[r] + e1bhh[r];
        for (int e = 0; e < 512; e++) acc = fmaf(wr[e], encb[e], acc);
        g_b1[n] = acc;
    }
}

__global__ void prep_x(const float* __restrict__ x) {
    long idx = (long)blockIdx.x * 256 + threadIdx.x;
    if (idx >= (long)TT * BB * 64) return;
    int c = (int)(idx & 63);
    int b = (int)((idx >> 6) & (BB - 1));
    int t = (int)(idx >> 17);
    float v = (c < POSE) ? x[(long)b * (TT * POSE) + t * POSE + c] : 0.f;
    g_x[idx] = __float2half_rn(v);
}

__global__ void zero_init() {
    long i = (long)blockIdx.x * 256 + threadIdx.x;
    if (i < (long)BE) {
        __half z = __float2half_rn(0.f);
        g_h1[0][i] = z;
        g_h2[0][i] = z;
        g_c1[i] = 0.f; g_c2[i] = 0.f;
    }
}

__global__ void final_linear(const float* __restrict__ preds,
                             const float* __restrict__ W, const float* __restrict__ bias,
                             float* __restrict__ out)
{
    int bf = blockIdx.x;
    int f = bf % FUT;
    int b = bf / FUT;
    __shared__ float row[512];
    const float* src = preds + ((size_t)f * BB + b) * EE;
    for (int i = threadIdx.x; i < 512; i += blockDim.x) row[i] = src[i];
    __syncthreads();
    int p = threadIdx.x;
    if (p < POSE) {
        const float* w = W + (size_t)p * 512;
        float acc = bias[p];
        for (int e = 0; e < 512; e++) acc = fmaf(row[e], w[e], acc);
        out[(size_t)b * (FUT * POSE) + f * POSE + p] = acc;
    }
}

// ============ launch ============
extern "C" void kernel_launch(void* const* d_in, const int* in_sizes, int n_in,
                              void* d_out, int out_size)
{
    (void)in_sizes; (void)n_in; (void)out_size;
    const float* x     = (const float*)d_in[0];
    const float* encW  = (const float*)d_in[1];
    const float* encb  = (const float*)d_in[2];
    const float* e1Wih = (const float*)d_in[3];
    const float* e1Whh = (const float*)d_in[4];
    const float* e1bih = (const float*)d_in[5];
    const float* e1bhh = (const float*)d_in[6];
    const float* e2Wih = (const float*)d_in[7];
    const float* e2Whh = (const float*)d_in[8];
    const float* e2bih = (const float*)d_in[9];
    const float* e2bhh = (const float*)d_in[10];
    const float* d1Wih = (const float*)d_in[11];
    const float* d1Whh = (const float*)d_in[12];
    const float* d1bih = (const float*)d_in[13];
    const float* d1bhh = (const float*)d_in[14];
    const float* dW    = (const float*)d_in[15];
    const float* db    = (const float*)d_in[16];
    float* out = (float*)d_out;

    __half *h1, *h2, *dh, *W1, *W2, *WD1, *WDr, *xh;
    float *c1, *c2, *b1, *b2, *bd, *preds;
    cudaGetSymbolAddress((void**)&h1,  g_h1);
    cudaGetSymbolAddress((void**)&h2,  g_h2);
    cudaGetSymbolAddress((void**)&dh,  g_dh);
    cudaGetSymbolAddress((void**)&c1,  g_c1);   cudaGetSymbolAddress((void**)&c2,  g_c2);
    cudaGetSymbolAddress((void**)&W1,  g_W1);   cudaGetSymbolAddress((void**)&W2,  g_W2);
    cudaGetSymbolAddress((void**)&WD1, g_WD1);  cudaGetSymbolAddress((void**)&WDr, g_WDr);
    cudaGetSymbolAddress((void**)&xh,  g_x);
    cudaGetSymbolAddress((void**)&b1,  g_b1);   cudaGetSymbolAddress((void**)&b2,  g_b2);
    cudaGetSymbolAddress((void**)&bd,  g_bd);   cudaGetSymbolAddress((void**)&preds, g_preds);

    cudaFuncSetAttribute(lstm_mma_step, cudaFuncAttributeMaxDynamicSharedMemorySize, SMEM_TOTAL);

    prep_weights<<<dim3((K1 + K2 + 2 * KD + 255) / 256, 2048), 256>>>(
        e1Whh, e2Wih, e2Whh, d1Wih, d1Whh, e2bih, e2bhh, d1bih, d1bhh);
    prep_wc<<<2048, 64>>>(e1Wih, encW, encb, e1bih, e1bhh);
    prep_x<<<(int)(((long)TT * BB * 64 + 255) / 256), 256>>>(x);
    zero_init<<<(BE + 255) / 256, 256>>>();

    dim3 grid(16, 16);
    for (int t = 0; t < TT; t++) {
        int in = t & 1, ot = (t + 1) & 1;
        // cell 1: A = [h1 | x_t slab], K = 576
        lstm_mma_step<<<grid, 128, SMEM_TOTAL>>>(
            h1 + (size_t)in * BE, EE,
            xh + (size_t)t * BB * 64, 64,
            512, K1, W1, K1, b1, c1,
            h1 + (size_t)ot * BE, nullptr);
        // cell 2: A = [h1_new | h2], K = 1024
        lstm_mma_step<<<grid, 128, SMEM_TOTAL>>>(
            h1 + (size_t)ot * BE, EE,
            h2 + (size_t)in * BE, EE,
            512, K2, W2, K2, b2, c2,
            h2 + (size_t)ot * BE, nullptr);
    }
    // encoder final h2/c2 in slot 0 (t=99 -> ot=0)

    // decoder step 0: input zeros -> gates = h2 @ Whh^T + bd
    lstm_mma_step<<<grid, 128, SMEM_TOTAL>>>(
        h2, EE, nullptr, 0,
        KD, KD, WD1, KD, bd, c2,
        dh, preds);
    // steps 1..9: out == h -> gates = h @ (Wih+Whh)^T + bd
    for (int f = 1; f < FUT; f++) {
        int ip = (f - 1) & 1, op = f & 1;
        lstm_mma_step<<<grid, 128, SMEM_TOTAL>>>(
            dh + (size_t)ip * BE, EE, nullptr, 0,
            KD, KD, WDr, KD, bd, c2,
            dh + (size_t)op * BE, preds + (size_t)f * BE);
    }

    final_linear<<<BB * FUT, 64>>>(preds, dW, db, out);
}

// round 9
// speedup vs baseline: 2.6647x; 1.0494x over previous
#include <cuda_runtime.h>
#include <cuda_fp16.h>
#include <stdint.h>
#include <stddef.h>

#define BB 2048
#define TT 100
#define EE 512
#define POSE 34
#define FUT 10
#define BE (BB*EE)

#define K1 576        // cell1: 512 (h1) + 64 (x slab: 34 real + pad)
#define K2 1024       // cell2: 512 (h1_new) + 512 (h2)
#define KD 512        // decoder

// SMEM pipeline: 5 stages x 16KB (A 8K | B 8K); single sync per chunk (WAR-safe at 5 stages)
#define STAGE_BYTES 16384
#define OFF_A 0
#define OFF_B 8192
#define NSTAGE 5
#define SMEM_TOTAL (NSTAGE*STAGE_BYTES)

// ---------------- device globals (no allocation allowed) ----------------
__device__ __align__(16) __half g_h1[2][BE];
__device__ __align__(16) __half g_h2[2][BE];
__device__ __align__(16) __half g_dh[2][BE];
__device__ __align__(16) float g_c1[BE], g_c2[BE];
__device__ __align__(16) __half g_W1[2048*K1];
__device__ __align__(16) __half g_W2[2048*K2];
__device__ __align__(16) __half g_WD1[2048*KD];
__device__ __align__(16) __half g_WDr[2048*KD];
__device__ __align__(16) __half g_x[(size_t)TT*BB*64];
__device__ __align__(16) float g_b1[2048], g_b2[2048], g_bd[2048];
__device__ __align__(16) float g_preds[(size_t)FUT*BE];

// ---------------- helpers ----------------
__device__ __forceinline__ float sigmoidf_(float x) { return __fdividef(1.f, 1.f + __expf(-x)); }
__device__ __forceinline__ float tanhf_(float x)    { return 1.f - __fdividef(2.f, __expf(2.f*x) + 1.f); }

__device__ __forceinline__ uint32_t smem_u32(const void* p) {
    uint32_t a;
    asm("{ .reg .u64 t; cvta.to.shared.u64 t, %1; cvt.u32.u64 %0, t; }" : "=r"(a) : "l"(p));
    return a;
}

// Interleaved tile layout: tile is 128 rows x 32 k (f16). Physical: 64 rows x 128B.
// element (row, kk): physrow r = row>>1, chunk = ((row&1)*4 + (kk>>3)) ^ (r&7),
// byte = r*128 + chunk*16 + (kk&7)*2.  Conflict-free for cp.async STS and ldmatrix.
__device__ __forceinline__ uint32_t tile_addr(uint32_t base, int row, int kk) {
    int r = row >> 1;
    int c = (((row & 1) << 2) + (kk >> 3)) ^ (r & 7);
    return base + (uint32_t)(r * 128 + c * 16 + (kk & 7) * 2);
}

__device__ __forceinline__ void cp16(uint32_t s, const void* g) {
    asm volatile("cp.async.cg.shared.global [%0], [%1], 16;" :: "r"(s), "l"(g));
}
__device__ __forceinline__ void cp_commit() { asm volatile("cp.async.commit_group;"); }
__device__ __forceinline__ void cp_wait3()  { asm volatile("cp.async.wait_group 3;"); }

__device__ __forceinline__ void ldsm4(uint32_t* d, uint32_t a) {
    asm volatile("ldmatrix.sync.aligned.m8n8.x4.shared.b16 {%0,%1,%2,%3}, [%4];"
        : "=r"(d[0]), "=r"(d[1]), "=r"(d[2]), "=r"(d[3]) : "r"(a));
}
__device__ __forceinline__ void mma_f16(float* d, const uint32_t* a, const uint32_t* b) {
    asm volatile("mma.sync.aligned.m16n8k16.row.col.f32.f16.f16.f32 "
        "{%0,%1,%2,%3}, {%4,%5,%6,%7}, {%8,%9}, {%0,%1,%2,%3};"
        : "+f"(d[0]), "+f"(d[1]), "+f"(d[2]), "+f"(d[3])
        : "r"(a[0]), "r"(a[1]), "r"(a[2]), "r"(a[3]), "r"(b[0]), "r"(b[1]));
}

// ============ fused mma.sync LSTM tile body (fp16, warp tile 64x64, 4 warps) ============
// gates[m][n] = sum_k A[m][k]*W[n][k] + bias[n]
// A = concat(A0[0:K0], A1[K0:Ktot]); n gate-interleaved: cols 4e..4e+3 = (i,f,g,o) of unit e.
__device__ __forceinline__ void lstm_tile_body(
    const __half* __restrict__ A0, int lda0,
    const __half* __restrict__ A1, int lda1,
    int K0, int Ktot,
    const __half* __restrict__ W, int ldw,
    const float* __restrict__ bias,
    float* __restrict__ c_inout,
    __half* __restrict__ H,
    float* __restrict__ Hf,
    int n0, int m0)
{
    extern __shared__ char smem[];
    const uint32_t sbase = smem_u32(smem);
    const int tid  = threadIdx.x;
    const int lane = tid & 31;
    const int warp = tid >> 5;         // 0..3
    const int wm = warp >> 1;          // 0..1  (m 64-half)
    const int wn = warp & 1;           // 0..1  (n 64-half)

    const int NC = Ktot >> 5;          // 32-k chunks

    // ---- stage issue: 8 cp.async per thread (A x4, B x4) ----
    auto issue = [&](int st) {
        const int kstW = st << 5;
        int kstA = kstW;
        const char* pA = (const char*)A0;
        int lda = lda0;
        if (kstA >= K0) { pA = (const char*)A1; lda = lda1; kstA -= K0; }
        const uint32_t sb = sbase + (uint32_t)((st % NSTAGE) * STAGE_BYTES);
#pragma unroll
        for (int p = 0; p < 4; p++) {
            const int ch = tid + p * 128;
            const int row = ch >> 2, c = ch & 3;
            cp16(tile_addr(sb + OFF_A, row, c * 8),
                 pA + ((size_t)(m0 + row) * lda + kstA + c * 8) * 2);
            cp16(tile_addr(sb + OFF_B, row, c * 8),
                 (const char*)W + ((size_t)(n0 + row) * ldw + kstW + c * 8) * 2);
        }
        cp_commit();
    };

    issue(0);
    issue(1);
    issue(2);

    float acc[32][4];                   // [i*8+jj][..]  i: m16 idx 0..3, jj: n8 idx 0..7
#pragma unroll
    for (int i = 0; i < 32; i++)
#pragma unroll
        for (int j = 0; j < 4; j++) acc[i][j] = 0.f;

    // lane-derived ldmatrix row/col offsets
    const int laA_r = lane & 15;            // row within m16
    const int laA_k = (lane >> 4) * 8;      // k half
    const int laB_r = (lane & 7) + ((lane >> 4) & 1) * 8;   // n within 16
    const int laB_k = ((lane >> 3) & 1) * 8;                // k half

    for (int cs = 0; cs < NC; cs++) {
        if (cs + 3 < NC) issue(cs + 3); else cp_commit();
        cp_wait3();
        __syncthreads();

        const uint32_t sb = sbase + (uint32_t)((cs % NSTAGE) * STAGE_BYTES);

#pragma unroll
        for (int h = 0; h < 2; h++) {
            const int kk0 = h * 16;
            uint32_t Af[4][4], Bf[16];
#pragma unroll
            for (int i = 0; i < 4; i++)
                ldsm4(Af[i], tile_addr(sb + OFF_A, wm * 64 + i * 16 + laA_r, kk0 + laA_k));
#pragma unroll
            for (int j = 0; j < 4; j++)
                ldsm4(&Bf[j * 4], tile_addr(sb + OFF_B, wn * 64 + j * 16 + laB_r, kk0 + laB_k));
#pragma unroll
            for (int i = 0; i < 4; i++)
#pragma unroll
                for (int jj = 0; jj < 8; jj++)
                    mma_f16(acc[i * 8 + jj], Af[i], &Bf[jj * 2]);
        }
    }

    // ---- fused LSTM epilogue (register-resident) ----
    // per 16x8 mma tile: lane covers rows (lane>>2)+{0,8}, col pair (lane&3)*2+{0,1}.
    // pair (lane, lane^1) jointly owns a gate quad; shfl_xor(1) assembles it.
    const int pairpos = lane & 1;
    const int rbase = lane >> 2;
    const int elocal = (lane >> 1) & 1;

#pragma unroll
    for (int i = 0; i < 4; i++) {
#pragma unroll
        for (int jj = 0; jj < 8; jj++) {
            float* a = acc[i * 8 + jj];
            float r0 = __shfl_xor_sync(0xffffffffu, a[0], 1);
            float r1 = __shfl_xor_sync(0xffffffffu, a[1], 1);
            float r2 = __shfl_xor_sync(0xffffffffu, a[2], 1);
            float r3 = __shfl_xor_sync(0xffffffffu, a[3], 1);
            float gi, gf, gg, go;
            if (pairpos == 0) { gi = a[0]; gf = a[1]; gg = r0; go = r1; }   // row rbase
            else              { gi = r2;  gf = r3;  gg = a[2]; go = a[3]; } // row rbase+8
            const int m = m0 + wm * 64 + i * 16 + rbase + pairpos * 8;
            const int e = ((n0 + wn * 64 + jj * 8) >> 2) + elocal;

            const float4 bq = ((const float4*)bias)[e];
            gi += bq.x; gf += bq.y; gg += bq.z; go += bq.w;

            const size_t off = (size_t)m * EE + e;
            const float co = c_inout[off];
            const float cn = sigmoidf_(gf) * co + sigmoidf_(gi) * tanhf_(gg);
            const float hn = sigmoidf_(go) * tanhf_(cn);
            c_inout[off] = cn;
            H[off] = __float2half_rn(hn);
            if (Hf) Hf[off] = hn;
        }
    }
}

// single-cell launch (prologue/tail/decoder)
__global__ void __launch_bounds__(128, 2)
lstm_mma_step(const __half* __restrict__ A0, int lda0,
              const __half* __restrict__ A1, int lda1,
              int K0, int Ktot,
              const __half* __restrict__ W, int ldw,
              const float* __restrict__ bias,
              float* __restrict__ c_inout,
              __half* __restrict__ H,
              float* __restrict__ Hf)
{
    lstm_tile_body(A0, lda0, A1, lda1, K0, Ktot, W, ldw, bias, c_inout, H, Hf,
                   blockIdx.x * 128, blockIdx.y * 128);
}

// merged launch: bids 0..255 = cell2(t) [job A], bids 256..511 = cell1(t+1) [job B].
// Both jobs share A0 = h1(t) with lda=EE, K0=512.
__global__ void __launch_bounds__(128, 2)
lstm_mma_pair(const __half* __restrict__ A0,
              const __half* __restrict__ A1a, int lda1a, int Kta,
              const __half* __restrict__ Wa, int ldwa,
              const float* __restrict__ ba, float* __restrict__ ca,
              __half* __restrict__ Ha,
              const __half* __restrict__ A1b, int lda1b, int Ktb,
              const __half* __restrict__ Wb, int ldwb,
              const float* __restrict__ bb, float* __restrict__ cb,
              __half* __restrict__ Hb)
{
    const int n0 = blockIdx.x * 128;
    const int m0 = (blockIdx.y & 15) * 128;
    if (blockIdx.y < 16)
        lstm_tile_body(A0, EE, A1a, lda1a, 512, Kta, Wa, ldwa, ba, ca, Ha, nullptr, n0, m0);
    else
        lstm_tile_body(A0, EE, A1b, lda1b, 512, Ktb, Wb, ldwb, bb, cb, Hb, nullptr, n0, m0);
}

// ============ prep kernels ============
// permuted gate col n -> original row r = (n%4)*512 + n/4  (quad (i,f,g,o) per hidden e)
__global__ void prep_weights(const float* __restrict__ e1Whh,
                             const float* __restrict__ e2Wih, const float* __restrict__ e2Whh,
                             const float* __restrict__ d1Wih, const float* __restrict__ d1Whh,
                             const float* __restrict__ e2bih, const float* __restrict__ e2bhh,
                             const float* __restrict__ d1bih, const float* __restrict__ d1bhh)
{
    int n = blockIdx.y;
    int kk = blockIdx.x * 256 + threadIdx.x;
    if (kk >= K1 + K2 + KD + KD) return;
    int r = (n & 3) * 512 + (n >> 2);
    float v; __half* ph; long o;
    if (kk < K1) {
        v = (kk < 512) ? e1Whh[(long)r * 512 + kk] : 0.f;   // 512..575 pad; 512..545 overwritten by prep_wc
        ph = g_W1; o = (long)n * K1 + kk;
    } else if (kk < K1 + K2) {
        int k = kk - K1;
        v = (k < 512) ? e2Wih[(long)r * 512 + k] : e2Whh[(long)r * 512 + (k - 512)];
        ph = g_W2; o = (long)n * K2 + k;
    } else if (kk < K1 + K2 + KD) {
        int k = kk - (K1 + K2);
        v = d1Whh[(long)r * 512 + k];
        ph = g_WD1; o = (long)n * KD + k;
    } else {
        int k = kk - (K1 + K2 + KD);
        v = d1Wih[(long)r * 512 + k] + d1Whh[(long)r * 512 + k];
        ph = g_WDr; o = (long)n * KD + k;
    }
    ph[o] = __float2half_rn(v);
    if (kk == 0) {
        g_b2[n] = e2bih[r] + e2bhh[r];
        g_bd[n] = d1bih[r] + d1bhh[r];
    }
}

// Wc = e1Wih @ enc_lin_W folded into W1 rows 512..545; b1 = e1Wih·enc_b + biases
__global__ void prep_wc(const float* __restrict__ e1Wih,
                        const float* __restrict__ encW, const float* __restrict__ encb,
                        const float* __restrict__ e1bih, const float* __restrict__ e1bhh)
{
    int n = blockIdx.x;
    int r = (n & 3) * 512 + (n >> 2);
    __shared__ float wr[512];
    for (int e = threadIdx.x; e < 512; e += blockDim.x) wr[e] = e1Wih[(long)r * 512 + e];
    __syncthreads();
    int t = threadIdx.x;
    if (t < POSE) {
        float acc = 0.f;
        for (int e = 0; e < 512; e++) acc = fmaf(wr[e], encW[e * POSE + t], acc);
        g_W1[(long)n * K1 + 512 + t] = __float2half_rn(acc);
    } else if (t == POSE) {
        float acc = e1bih[r] + e1bhh[r];
        for (int e = 0; e < 512; e++) acc = fmaf(wr[e], encb[e], acc);
        g_b1[n] = acc;
    }
}

__global__ void prep_x(const float* __restrict__ x) {
    long idx = (long)blockIdx.x * 256 + threadIdx.x;
    if (idx >= (long)TT * BB * 64) return;
    int c = (int)(idx & 63);
    int b = (int)((idx >> 6) & (BB - 1));
    int t = (int)(idx >> 17);
    float v = (c < POSE) ? x[(long)b * (TT * POSE) + t * POSE + c] : 0.f;
    g_x[idx] = __float2half_rn(v);
}

__global__ void zero_init() {
    long i = (long)blockIdx.x * 256 + threadIdx.x;
    if (i < (long)BE) {
        __half z = __float2half_rn(0.f);
        g_h1[0][i] = z;
        g_h2[0][i] = z;
        g_c1[i] = 0.f; g_c2[i] = 0.f;
    }
}

__global__ void final_linear(const float* __restrict__ preds,
                             const float* __restrict__ W, const float* __restrict__ bias,
                             float* __restrict__ out)
{
    int bf = blockIdx.x;
    int f = bf % FUT;
    int b = bf / FUT;
    __shared__ float row[512];
    const float* src = preds + ((size_t)f * BB + b) * EE;
    for (int i = threadIdx.x; i < 512; i += blockDim.x) row[i] = src[i];
    __syncthreads();
    int p = threadIdx.x;
    if (p < POSE) {
        const float* w = W + (size_t)p * 512;
        float acc = bias[p];
        for (int e = 0; e < 512; e++) acc = fmaf(row[e], w[e], acc);
        out[(size_t)b * (FUT * POSE) + f * POSE + p] = acc;
    }
}

// ============ launch ============
extern "C" void kernel_launch(void* const* d_in, const int* in_sizes, int n_in,
                              void* d_out, int out_size)
{
    (void)in_sizes; (void)n_in; (void)out_size;
    const float* x     = (const float*)d_in[0];
    const float* encW  = (const float*)d_in[1];
    const float* encb  = (const float*)d_in[2];
    const float* e1Wih = (const float*)d_in[3];
    const float* e1Whh = (const float*)d_in[4];
    const float* e1bih = (const float*)d_in[5];
    const float* e1bhh = (const float*)d_in[6];
    const float* e2Wih = (const float*)d_in[7];
    const float* e2Whh = (const float*)d_in[8];
    const float* e2bih = (const float*)d_in[9];
    const float* e2bhh = (const float*)d_in[10];
    const float* d1Wih = (const float*)d_in[11];
    const float* d1Whh = (const float*)d_in[12];
    const float* d1bih = (const float*)d_in[13];
    const float* d1bhh = (const float*)d_in[14];
    const float* dW    = (const float*)d_in[15];
    const float* db    = (const float*)d_in[16];
    float* out = (float*)d_out;

    __half *h1, *h2, *dh, *W1, *W2, *WD1, *WDr, *xh;
    float *c1, *c2, *b1, *b2, *bd, *preds;
    cudaGetSymbolAddress((void**)&h1,  g_h1);
    cudaGetSymbolAddress((void**)&h2,  g_h2);
    cudaGetSymbolAddress((void**)&dh,  g_dh);
    cudaGetSymbolAddress((void**)&c1,  g_c1);   cudaGetSymbolAddress((void**)&c2,  g_c2);
    cudaGetSymbolAddress((void**)&W1,  g_W1);   cudaGetSymbolAddress((void**)&W2,  g_W2);
    cudaGetSymbolAddress((void**)&WD1, g_WD1);  cudaGetSymbolAddress((void**)&WDr, g_WDr);
    cudaGetSymbolAddress((void**)&xh,  g_x);
    cudaGetSymbolAddress((void**)&b1,  g_b1);   cudaGetSymbolAddress((void**)&b2,  g_b2);
    cudaGetSymbolAddress((void**)&bd,  g_bd);   cudaGetSymbolAddress((void**)&preds, g_preds);

    cudaFuncSetAttribute(lstm_mma_step, cudaFuncAttributeMaxDynamicSharedMemorySize, SMEM_TOTAL);
    cudaFuncSetAttribute(lstm_mma_pair, cudaFuncAttributeMaxDynamicSharedMemorySize, SMEM_TOTAL);

    zero_init<<<(BE + 255) / 256, 256>>>();
    prep_weights<<<dim3((K1 + K2 + 2 * KD + 255) / 256, 2048), 256>>>(
        e1Whh, e2Wih, e2Whh, d1Wih, d1Whh, e2bih, e2bhh, d1bih, d1bhh);
    prep_wc<<<2048, 64>>>(e1Wih, encW, encb, e1bih, e1bhh);
    prep_x<<<(int)(((long)TT * BB * 64 + 255) / 256), 256>>>(x);

    dim3 grid1(16, 16);
    dim3 grid2(16, 32);

    // prologue: cell1(0): A = [h1(-1)=0 | x_0], writes h1(0) -> slot1
    lstm_mma_step<<<grid1, 128, SMEM_TOTAL>>>(
        h1, EE, xh, 64, 512, K1, W1, K1, b1, c1, h1 + BE, nullptr);

    // merged steps t=0..98: jobA = cell2(t), jobB = cell1(t+1)
    // h1(t) lives in slot (t+1)&1; h2(t) in slot (t+1)&1.
    for (int t = 0; t < TT - 1; t++) {
        const __half* h1t = h1 + (size_t)((t + 1) & 1) * BE;
        lstm_mma_pair<<<grid2, 128, SMEM_TOTAL>>>(
            h1t,
            // job A: cell2(t): A1 = h2(t-1) slot t&1, writes h2(t) slot (t+1)&1
            h2 + (size_t)(t & 1) * BE, EE, K2, W2, K2, b2, c2,
            h2 + (size_t)((t + 1) & 1) * BE,
            // job B: cell1(t+1): A1 = x_{t+1}, writes h1(t+1) slot t&1
            xh + (size_t)(t + 1) * BB * 64, 64, K1, W1, K1, b1, c1,
            h1 + (size_t)(t & 1) * BE);
    }

    // tail: cell2(99): A = [h1(99) slot0 | h2(98) slot1], writes h2(99) -> slot0
    lstm_mma_step<<<grid1, 128, SMEM_TOTAL>>>(
        h1, EE, h2 + BE, EE, 512, K2, W2, K2, b2, c2, h2, nullptr);

    // decoder step 0: input zeros -> gates = h2 @ Whh^T + bd
    lstm_mma_step<<<grid1, 128, SMEM_TOTAL>>>(
        h2, EE, nullptr, 0,
        KD, KD, WD1, KD, bd, c2,
        dh, preds);
    // steps 1..9: out == h -> gates = h @ (Wih+Whh)^T + bd
    for (int f = 1; f < FUT; f++) {
        int ip = (f - 1) & 1, op = f & 1;
        lstm_mma_step<<<grid1, 128, SMEM_TOTAL>>>(
            dh + (size_t)ip * BE, EE, nullptr, 0,
            KD, KD, WDr, KD, bd, c2,
            dh + (size_t)op * BE, preds + (size_t)f * BE);
    }

    final_linear<<<BB * FUT, 64>>>(preds, dW, db, out);
}

// round 10
// speedup vs baseline: 2.8476x; 1.0686x over previous
#include <cuda_runtime.h>
#include <cuda_fp16.h>
#include <stdint.h>
#include <stddef.h>

#define BB 2048
#define TT 100
#define EE 512
#define POSE 34
#define FUT 10
#define BE (BB*EE)

#define K1 576        // cell1: 512 (h1) + 64 (x slab: 34 real + pad)
#define K2 1024       // cell2: 512 (h1_new) + 512 (h2)
#define KD 512        // decoder

#define NCTA 256      // persistent grid; 2/SM on 128 SMs, all co-resident (capacity 296)

// SMEM pipeline: 5 stages x 16KB (A 8K | B 8K); single sync per chunk (WAR-safe at 5 stages)
#define STAGE_BYTES 16384
#define OFF_A 0
#define OFF_B 8192
#define NSTAGE 5
#define SMEM_TOTAL (NSTAGE*STAGE_BYTES)

// ---------------- device globals (no allocation allowed) ----------------
__device__ __align__(16) __half g_h1[2][BE];     // h1(t) lives in slot t&1
__device__ __align__(16) __half g_h2[2][BE];     // h2(t) lives in slot t&1
__device__ __align__(16) __half g_dh[2][BE];     // decoder h, slot f&1
__device__ __align__(16) float g_c1[BE], g_c2[BE];
__device__ __align__(16) __half g_W1[2048*K1];
__device__ __align__(16) __half g_W2[2048*K2];
__device__ __align__(16) __half g_WD1[2048*KD];
__device__ __align__(16) __half g_WDr[2048*KD];
__device__ __align__(16) __half g_x[(size_t)TT*BB*64];
__device__ __align__(16) float g_b1[2048], g_b2[2048], g_bd[2048];
__device__ __align__(16) float g_preds[(size_t)FUT*BE];

// global barrier state (returns to cnt=0 after every barrier -> graph-replay safe)
__device__ unsigned g_cnt = 0;
__device__ volatile unsigned g_gen = 0;

// ---------------- helpers ----------------
__device__ __forceinline__ float sigmoidf_(float x) { return __fdividef(1.f, 1.f + __expf(-x)); }
__device__ __forceinline__ float tanhf_(float x)    { return 1.f - __fdividef(2.f, __expf(2.f*x) + 1.f); }

__device__ __forceinline__ uint32_t smem_u32(const void* p) {
    uint32_t a;
    asm("{ .reg .u64 t; cvta.to.shared.u64 t, %1; cvt.u32.u64 %0, t; }" : "=r"(a) : "l"(p));
    return a;
}

// Interleaved tile layout: tile is 128 rows x 32 k (f16). Physical: 64 rows x 128B.
// element (row, kk): physrow r = row>>1, chunk = ((row&1)*4 + (kk>>3)) ^ (r&7),
// byte = r*128 + chunk*16 + (kk&7)*2.  Conflict-free for cp.async STS and ldmatrix.
__device__ __forceinline__ uint32_t tile_addr(uint32_t base, int row, int kk) {
    int r = row >> 1;
    int c = (((row & 1) << 2) + (kk >> 3)) ^ (r & 7);
    return base + (uint32_t)(r * 128 + c * 16 + (kk & 7) * 2);
}

__device__ __forceinline__ void cp16(uint32_t s, const void* g) {
    asm volatile("cp.async.cg.shared.global [%0], [%1], 16;" :: "r"(s), "l"(g));
}
__device__ __forceinline__ void cp_commit() { asm volatile("cp.async.commit_group;"); }
__device__ __forceinline__ void cp_wait3()  { asm volatile("cp.async.wait_group 3;"); }
__device__ __forceinline__ void cp_wait0()  { asm volatile("cp.async.wait_group 0;"); }

__device__ __forceinline__ void ldsm4(uint32_t* d, uint32_t a) {
    asm volatile("ldmatrix.sync.aligned.m8n8.x4.shared.b16 {%0,%1,%2,%3}, [%4];"
        : "=r"(d[0]), "=r"(d[1]), "=r"(d[2]), "=r"(d[3]) : "r"(a));
}
__device__ __forceinline__ void mma_f16(float* d, const uint32_t* a, const uint32_t* b) {
    asm volatile("mma.sync.aligned.m16n8k16.row.col.f32.f16.f16.f32 "
        "{%0,%1,%2,%3}, {%4,%5,%6,%7}, {%8,%9}, {%0,%1,%2,%3};"
        : "+f"(d[0]), "+f"(d[1]), "+f"(d[2]), "+f"(d[3])
        : "r"(a[0]), "r"(a[1]), "r"(a[2]), "r"(a[3]), "r"(b[0]), "r"(b[1]));
}

// device-wide sense-reversing barrier (all NCTA CTAs co-resident)
__device__ __forceinline__ void grid_bar() {
    __syncthreads();
    if (threadIdx.x == 0) {
        __threadfence();
        unsigned my = g_gen;
        if (atomicAdd(&g_cnt, 1u) == NCTA - 1u) {
            atomicExch(&g_cnt, 0u);
            __threadfence();
            g_gen = my + 1u;
        } else {
            while (g_gen == my) {}
        }
        __threadfence();
    }
    __syncthreads();
}

// ============ fused mma.sync LSTM tile body (fp16, warp tile 64x64, 4 warps) ============
// gates[m][n] = sum_k A[m][k]*W[n][k] + bias[n]
// A = concat(A0[0:K0], A1[K0:Ktot]); n gate-interleaved: cols 4e..4e+3 = (i,f,g,o) of unit e.
__device__ __forceinline__ void lstm_tile_body(
    const __half* __restrict__ A0, int lda0,
    const __half* __restrict__ A1, int lda1,
    int K0, int Ktot,
    const __half* __restrict__ W, int ldw,
    const float* __restrict__ bias,
    float* __restrict__ c_inout,
    __half* __restrict__ H,
    float* __restrict__ Hf,
    int n0, int m0)
{
    extern __shared__ char smem[];
    const uint32_t sbase = smem_u32(smem);
    const int tid  = threadIdx.x;
    const int lane = tid & 31;
    const int warp = tid >> 5;         // 0..3
    const int wm = warp >> 1;          // 0..1  (m 64-half)
    const int wn = warp & 1;           // 0..1  (n 64-half)

    const int NC = Ktot >> 5;          // 32-k chunks

    // ---- stage issue: 8 cp.async per thread (A x4, B x4) ----
    auto issue = [&](int st) {
        const int kstW = st << 5;
        int kstA = kstW;
        const char* pA = (const char*)A0;
        int lda = lda0;
        if (kstA >= K0) { pA = (const char*)A1; lda = lda1; kstA -= K0; }
        const uint32_t sb = sbase + (uint32_t)((st % NSTAGE) * STAGE_BYTES);
#pragma unroll
        for (int p = 0; p < 4; p++) {
            const int ch = tid + p * 128;
            const int row = ch >> 2, c = ch & 3;
            cp16(tile_addr(sb + OFF_A, row, c * 8),
                 pA + ((size_t)(m0 + row) * lda + kstA + c * 8) * 2);
            cp16(tile_addr(sb + OFF_B, row, c * 8),
                 (const char*)W + ((size_t)(n0 + row) * ldw + kstW + c * 8) * 2);
        }
        cp_commit();
    };

    issue(0);
    issue(1);
    issue(2);

    float acc[32][4];                   // [i*8+jj][..]  i: m16 idx 0..3, jj: n8 idx 0..7
#pragma unroll
    for (int i = 0; i < 32; i++)
#pragma unroll
        for (int j = 0; j < 4; j++) acc[i][j] = 0.f;

    // lane-derived ldmatrix row/col offsets
    const int laA_r = lane & 15;            // row within m16
    const int laA_k = (lane >> 4) * 8;      // k half
    const int laB_r = (lane & 7) + ((lane >> 4) & 1) * 8;   // n within 16
    const int laB_k = ((lane >> 3) & 1) * 8;                // k half

    for (int cs = 0; cs < NC; cs++) {
        if (cs + 3 < NC) issue(cs + 3); else cp_commit();
        cp_wait3();
        __syncthreads();

        const uint32_t sb = sbase + (uint32_t)((cs % NSTAGE) * STAGE_BYTES);

#pragma unroll
        for (int h = 0; h < 2; h++) {
            const int kk0 = h * 16;
            uint32_t Af[4][4], Bf[16];
#pragma unroll
            for (int i = 0; i < 4; i++)
                ldsm4(Af[i], tile_addr(sb + OFF_A, wm * 64 + i * 16 + laA_r, kk0 + laA_k));
#pragma unroll
            for (int j = 0; j < 4; j++)
                ldsm4(&Bf[j * 4], tile_addr(sb + OFF_B, wn * 64 + j * 16 + laB_r, kk0 + laB_k));
#pragma unroll
            for (int i = 0; i < 4; i++)
#pragma unroll
                for (int jj = 0; jj < 8; jj++)
                    mma_f16(acc[i * 8 + jj], Af[i], &Bf[jj * 2]);
        }
    }
    cp_wait0();   // drain outstanding prefetches before smem is reused next call

    // ---- fused LSTM epilogue (register-resident) ----
    // per 16x8 mma tile: lane covers rows (lane>>2)+{0,8}, col pair (lane&3)*2+{0,1}.
    // pair (lane, lane^1) jointly owns a gate quad; shfl_xor(1) assembles it.
    const int pairpos = lane & 1;
    const int rbase = lane >> 2;
    const int elocal = (lane >> 1) & 1;

#pragma unroll
    for (int i = 0; i < 4; i++) {
#pragma unroll
        for (int jj = 0; jj < 8; jj++) {
            float* a = acc[i * 8 + jj];
            float r0 = __shfl_xor_sync(0xffffffffu, a[0], 1);
            float r1 = __shfl_xor_sync(0xffffffffu, a[1], 1);
            float r2 = __shfl_xor_sync(0xffffffffu, a[2], 1);
            float r3 = __shfl_xor_sync(0xffffffffu, a[3], 1);
            float gi, gf, gg, go;
            if (pairpos == 0) { gi = a[0]; gf = a[1]; gg = r0; go = r1; }   // row rbase
            else              { gi = r2;  gf = r3;  gg = a[2]; go = a[3]; } // row rbase+8
            const int m = m0 + wm * 64 + i * 16 + rbase + pairpos * 8;
            const int e = ((n0 + wn * 64 + jj * 8) >> 2) + elocal;

            const float4 bq = ((const float4*)bias)[e];
            gi += bq.x; gf += bq.y; gg += bq.z; go += bq.w;

            const size_t off = (size_t)m * EE + e;
            const float co = c_inout[off];
            const float cn = sigmoidf_(gf) * co + sigmoidf_(gi) * tanhf_(gg);
            const float hn = sigmoidf_(go) * tanhf_(cn);
            c_inout[off] = cn;
            H[off] = __float2half_rn(hn);
            if (Hf) Hf[off] = hn;
        }
    }
}

// ============ the persistent kernel: whole recurrence in one launch ============
__global__ void __launch_bounds__(128, 2)
lstm_persistent()
{
    const int n0 = (blockIdx.x & 15) * 128;
    const int m0 = (blockIdx.x >> 4) * 128;

    const __half* h1b = (const __half*)g_h1;
    const __half* h2b = (const __half*)g_h2;

    // encoder: phase ph runs cell2(ph-1) then cell1(ph)
    for (int ph = 0; ph <= TT; ph++) {
#pragma unroll 1
        for (int j = 0; j < 2; j++) {
            const bool act = (j == 0) ? (ph >= 1) : (ph < TT);
            if (!act) continue;
            const int t = (j == 0) ? ph - 1 : ph;
            const __half* a0 = h1b + (size_t)(((j == 0) ? t : (t + 1)) & 1) * BE;
            const __half* a1 = (j == 0) ? (h2b + (size_t)((t + 1) & 1) * BE)
                                        : (g_x + (size_t)t * BB * 64);
            const int lda1   = (j == 0) ? EE : 64;
            const int kt     = (j == 0) ? K2 : K1;
            const __half* w  = (j == 0) ? g_W2 : g_W1;
            const float* bs  = (j == 0) ? g_b2 : g_b1;
            float* cc        = (j == 0) ? g_c2 : g_c1;
            __half* hh       = (j == 0) ? (g_h2[t & 1]) : (g_h1[t & 1]);
            lstm_tile_body(a0, EE, a1, lda1, 512, kt, w, kt, bs, cc, hh, nullptr, n0, m0);
        }
        grid_bar();
    }

    // decoder: f=0 uses Whh only with A=h2(99) (slot 1); f>=1 uses (Wih+Whh) with A=dh(f-1)
#pragma unroll 1
    for (int f = 0; f < FUT; f++) {
        const __half* a0 = (f == 0) ? (h2b + (size_t)BE)
                                    : ((const __half*)g_dh + (size_t)((f + 1) & 1) * BE);
        const __half* w  = (f == 0) ? g_WD1 : g_WDr;
        lstm_tile_body(a0, EE, nullptr, 0, KD, KD, w, KD, g_bd, g_c2,
                       g_dh[f & 1], g_preds + (size_t)f * BE, n0, m0);
        grid_bar();
    }
}

// ============ prep kernels ============
// permuted gate col n -> original row r = (n%4)*512 + n/4  (quad (i,f,g,o) per hidden e)
__global__ void prep_weights(const float* __restrict__ e1Whh,
                             const float* __restrict__ e2Wih, const float* __restrict__ e2Whh,
                             const float* __restrict__ d1Wih, const float* __restrict__ d1Whh,
                             const float* __restrict__ e2bih, const float* __restrict__ e2bhh,
                             const float* __restrict__ d1bih, const float* __restrict__ d1bhh)
{
    int n = blockIdx.y;
    int kk = blockIdx.x * 256 + threadIdx.x;
    if (kk >= K1 + K2 + KD + KD) return;
    int r = (n & 3) * 512 + (n >> 2);
    float v; __half* ph; long o;
    if (kk < K1) {
        v = (kk < 512) ? e1Whh[(long)r * 512 + kk] : 0.f;   // 512..575 pad; 512..545 overwritten by prep_wc
        ph = g_W1; o = (long)n * K1 + kk;
    } else if (kk < K1 + K2) {
        int k = kk - K1;
        v = (k < 512) ? e2Wih[(long)r * 512 + k] : e2Whh[(long)r * 512 + (k - 512)];
        ph = g_W2; o = (long)n * K2 + k;
    } else if (kk < K1 + K2 + KD) {
        int k = kk - (K1 + K2);
        v = d1Whh[(long)r * 512 + k];
        ph = g_WD1; o = (long)n * KD + k;
    } else {
        int k = kk - (K1 + K2 + KD);
        v = d1Wih[(long)r * 512 + k] + d1Whh[(long)r * 512 + k];
        ph = g_WDr; o = (long)n * KD + k;
    }
    ph[o] = __float2half_rn(v);
    if (kk == 0) {
        g_b2[n] = e2bih[r] + e2bhh[r];
        g_bd[n] = d1bih[r] + d1bhh[r];
    }
}

// Wc = e1Wih @ enc_lin_W folded into W1 rows 512..545; b1 = e1Wih·enc_b + biases
__global__ void prep_wc(const float* __restrict__ e1Wih,
                        const float* __restrict__ encW, const float* __restrict__ encb,
                        const float* __restrict__ e1bih, const float* __restrict__ e1bhh)
{
    int n = blockIdx.x;
    int r = (n & 3) * 512 + (n >> 2);
    __shared__ float wr[512];
    for (int e = threadIdx.x; e < 512; e += blockDim.x) wr[e] = e1Wih[(long)r * 512 + e];
    __syncthreads();
    int t = threadIdx.x;
    if (t < POSE) {
        float acc = 0.f;
        for (int e = 0; e < 512; e++) acc = fmaf(wr[e], encW[e * POSE + t], acc);
        g_W1[(long)n * K1 + 512 + t] = __float2half_rn(acc);
    } else if (t == POSE) {
        float acc = e1bih[r] + e1bhh[r];
        for (int e = 0; e < 512; e++) acc = fmaf(wr[e], encb[e], acc);
        g_b1[n] = acc;
    }
}

__global__ void prep_x(const float* __restrict__ x) {
    long idx = (long)blockIdx.x * 256 + threadIdx.x;
    if (idx >= (long)TT * BB * 64) return;
    int c = (int)(idx & 63);
    int b = (int)((idx >> 6) & (BB - 1));
    int t = (int)(idx >> 17);
    float v = (c < POSE) ? x[(long)b * (TT * POSE) + t * POSE + c] : 0.f;
    g_x[idx] = __float2half_rn(v);
}

__global__ void zero_init() {
    long i = (long)blockIdx.x * 256 + threadIdx.x;
    if (i < (long)BE) {
        __half z = __float2half_rn(0.f);
        g_h1[1][i] = z;     // h1(-1) read from slot 1
        g_h2[1][i] = z;     // h2(-1) read from slot 1
        g_c1[i] = 0.f; g_c2[i] = 0.f;
    }
}

__global__ void final_linear(const float* __restrict__ preds,
                             const float* __restrict__ W, const float* __restrict__ bias,
                             float* __restrict__ out)
{
    int bf = blockIdx.x;
    int f = bf % FUT;
    int b = bf / FUT;
    __shared__ float row[512];
    const float* src = preds + ((size_t)f * BB + b) * EE;
    for (int i = threadIdx.x; i < 512; i += blockDim.x) row[i] = src[i];
    __syncthreads();
    int p = threadIdx.x;
    if (p < POSE) {
        const float* w = W + (size_t)p * 512;
        float acc = bias[p];
        for (int e = 0; e < 512; e++) acc = fmaf(row[e], w[e], acc);
        out[(size_t)b * (FUT * POSE) + f * POSE + p] = acc;
    }
}

// ============ launch ============
extern "C" void kernel_launch(void* const* d_in, const int* in_sizes, int n_in,
                              void* d_out, int out_size)
{
    (void)in_sizes; (void)n_in; (void)out_size;
    const float* x     = (const float*)d_in[0];
    const float* encW  = (const float*)d_in[1];
    const float* encb  = (const float*)d_in[2];
    const float* e1Wih = (const float*)d_in[3];
    const float* e1Whh = (const float*)d_in[4];
    const float* e1bih = (const float*)d_in[5];
    const float* e1bhh = (const float*)d_in[6];
    const float* e2Wih = (const float*)d_in[7];
    const float* e2Whh = (const float*)d_in[8];
    const float* e2bih = (const float*)d_in[9];
    const float* e2bhh = (const float*)d_in[10];
    const float* d1Wih = (const float*)d_in[11];
    const float* d1Whh = (const float*)d_in[12];
    const float* d1bih = (const float*)d_in[13];
    const float* d1bhh = (const float*)d_in[14];
    const float* dW    = (const float*)d_in[15];
    const float* db    = (const float*)d_in[16];
    float* out = (float*)d_out;

    float* preds;
    cudaGetSymbolAddress((void**)&preds, g_preds);

    cudaFuncSetAttribute(lstm_persistent, cudaFuncAttributeMaxDynamicSharedMemorySize, SMEM_TOTAL);

    zero_init<<<(BE + 255) / 256, 256>>>();
    prep_weights<<<dim3((K1 + K2 + 2 * KD + 255) / 256, 2048), 256>>>(
        e1Whh, e2Wih, e2Whh, d1Wih, d1Whh, e2bih, e2bhh, d1bih, d1bhh);
    prep_wc<<<2048, 64>>>(e1Wih, encW, encb, e1bih, e1bhh);
    prep_x<<<(int)(((long)TT * BB * 64 + 255) / 256), 256>>>(x);

    // entire recurrence: one persistent launch, device-wide barriers between phases
    lstm_persistent<<<NCTA, 128, SMEM_TOTAL>>>();

    final_linear<<<BB * FUT, 64>>>(preds, dW, db, out);
}